// round 1
// baseline (speedup 1.0000x reference)
#include <cuda_runtime.h>
#include <math.h>

#define ATOMS_MAX 50000
#define EDGES_MAX 1600000
#define BN_EPS 1e-5f

// ---------------- scratch (device globals; no allocation allowed) ----------------
__device__ __align__(16) float g_Pself[ATOMS_MAX * 128];                 // 25.6 MB
__device__ __align__(16) float g_Pnbr [ATOMS_MAX * 128];                 // 25.6 MB
__device__ __align__(16) float g_y[(size_t)EDGES_MAX * 128];             // 819 MB
__device__ __align__(16) float g_ns[ATOMS_MAX * 64];                     // 12.8 MB
__device__ int   g_start[ATOMS_MAX + 1];
__device__ float g_bn1s[128], g_bn1q[128], g_a1[128], g_c1[128];
__device__ float g_bn2s[64],  g_bn2q[64],  g_a2[64],  g_c2[64];

__device__ __forceinline__ float sigmoid_f(float x) {
    return 1.0f / (1.0f + __expf(-x));
}
__device__ __forceinline__ float softplus_f(float x) {
    // log(1+exp(x)) stable
    return fmaxf(x, 0.0f) + log1pf(__expf(-fabsf(x)));
}

// ---------------- k_init: zero stats, CSR sentinel ----------------
__global__ void k_init(int N, int E) {
    int i = blockIdx.x * blockDim.x + threadIdx.x;
    if (i < 128) { g_bn1s[i] = 0.f; g_bn1q[i] = 0.f; }
    if (i < 64)  { g_bn2s[i] = 0.f; g_bn2q[i] = 0.f; }
    if (i <= N)  g_start[i] = E;
}

// ---------------- k_proj: P = atom(N,64) @ Wp(64,128) ----------------
// which==0 -> g_Pself, which==1 -> g_Pnbr. Tile 64 atoms x 128 outputs.
__global__ __launch_bounds__(256) void k_proj(const float* __restrict__ atom,
                                              const float* __restrict__ Wp,
                                              int which, int N) {
    __shared__ __align__(16) float sW[64 * 128];   // 32 KB
    __shared__ float sA[64 * 33];                  // padded, 8.4 KB
    float* __restrict__ P = which ? g_Pnbr : g_Pself;

    int tid = threadIdx.x;
    int a0 = blockIdx.x * 64;
    for (int i = tid; i < 64 * 128; i += 256) sW[i] = Wp[i];

    int tx = tid & 15, ty = tid >> 4;
    int n0 = tx * 8, m0 = ty * 4;
    float acc[4][8];
#pragma unroll
    for (int i = 0; i < 4; i++)
#pragma unroll
        for (int j = 0; j < 8; j++) acc[i][j] = 0.f;

    for (int kc = 0; kc < 64; kc += 32) {
        __syncthreads();
        for (int i = tid; i < 64 * 32; i += 256) {
            int m = i >> 5, k = i & 31;
            int a = a0 + m;
            sA[m * 33 + k] = (a < N) ? atom[(size_t)a * 64 + kc + k] : 0.f;
        }
        __syncthreads();
#pragma unroll 8
        for (int k = 0; k < 32; k++) {
            float4 b0 = *(const float4*)&sW[(kc + k) * 128 + n0];
            float4 b1 = *(const float4*)&sW[(kc + k) * 128 + n0 + 4];
            float b[8] = {b0.x, b0.y, b0.z, b0.w, b1.x, b1.y, b1.z, b1.w};
#pragma unroll
            for (int i = 0; i < 4; i++) {
                float av = sA[(m0 + i) * 33 + k];
#pragma unroll
                for (int j = 0; j < 8; j++) acc[i][j] = fmaf(av, b[j], acc[i][j]);
            }
        }
    }
#pragma unroll
    for (int i = 0; i < 4; i++) {
        int a = a0 + m0 + i;
        if (a < N) {
            *(float4*)&P[(size_t)a * 128 + n0] =
                make_float4(acc[i][0], acc[i][1], acc[i][2], acc[i][3]);
            *(float4*)&P[(size_t)a * 128 + n0 + 4] =
                make_float4(acc[i][4], acc[i][5], acc[i][6], acc[i][7]);
        }
    }
}

// ---------------- k_edge: y = nbr@We + Pself[s] + Pnbr[n] + b ; BN1 stats ----------
// Tile: 128 edges x 128 outputs, K=32. 256 threads, 8x8 microtile.
__global__ __launch_bounds__(256) void k_edge(const float* __restrict__ nbr,
                                              const int* __restrict__ sidx,
                                              const int* __restrict__ nidx,
                                              const float* __restrict__ W,
                                              const float* __restrict__ bias,
                                              int E) {
    __shared__ __align__(16) float sW[32 * 128];   // 16 KB (W rows 128..159)
    __shared__ float sA[128 * 33];                 // 16.9 KB
    __shared__ float sB[128];
    __shared__ int   sS[128], sN[128];
    __shared__ float sred[16 * 128];               // 8 KB

    int tid = threadIdx.x;
    int e0 = blockIdx.x * 128;

    for (int i = tid; i < 32 * 128; i += 256) sW[i] = W[128 * 128 + i];
    for (int i = tid; i < 128 * 32; i += 256) {
        int m = i >> 5, k = i & 31;
        sA[m * 33 + k] = (e0 + m < E) ? nbr[(size_t)(e0 + m) * 32 + k] : 0.f;
    }
    if (tid < 128) {
        sB[tid] = bias[tid];
        int e = e0 + tid;
        sS[tid] = (e < E) ? sidx[e] : 0;
        sN[tid] = (e < E) ? nidx[e] : 0;
    }
    __syncthreads();

    int tx = tid & 15, ty = tid >> 4;
    int n0 = tx * 8, m0 = ty * 8;
    float acc[8][8];
#pragma unroll
    for (int i = 0; i < 8; i++)
#pragma unroll
        for (int j = 0; j < 8; j++) acc[i][j] = 0.f;

#pragma unroll 8
    for (int k = 0; k < 32; k++) {
        float4 b0 = *(const float4*)&sW[k * 128 + n0];
        float4 b1 = *(const float4*)&sW[k * 128 + n0 + 4];
        float b[8] = {b0.x, b0.y, b0.z, b0.w, b1.x, b1.y, b1.z, b1.w};
        float a[8];
#pragma unroll
        for (int i = 0; i < 8; i++) a[i] = sA[(m0 + i) * 33 + k];
#pragma unroll
        for (int i = 0; i < 8; i++)
#pragma unroll
            for (int j = 0; j < 8; j++) acc[i][j] = fmaf(a[i], b[j], acc[i][j]);
    }

    float bb[8];
#pragma unroll
    for (int j = 0; j < 8; j++) bb[j] = sB[n0 + j];

    float psum[8], psq[8];
#pragma unroll
    for (int j = 0; j < 8; j++) { psum[j] = 0.f; psq[j] = 0.f; }

#pragma unroll
    for (int i = 0; i < 8; i++) {
        int m = m0 + i;
        int e = e0 + m;
        if (e < E) {
            int s  = sS[m];
            int nb = sN[m];
            const float4* Ps = (const float4*)&g_Pself[(size_t)s  * 128 + n0];
            const float4* Pn = (const float4*)&g_Pnbr [(size_t)nb * 128 + n0];
            float4 p0 = Ps[0], p1 = Ps[1];
            float4 q0 = Pn[0], q1 = Pn[1];
            float yv[8];
            yv[0] = acc[i][0] + p0.x + q0.x + bb[0];
            yv[1] = acc[i][1] + p0.y + q0.y + bb[1];
            yv[2] = acc[i][2] + p0.z + q0.z + bb[2];
            yv[3] = acc[i][3] + p0.w + q0.w + bb[3];
            yv[4] = acc[i][4] + p1.x + q1.x + bb[4];
            yv[5] = acc[i][5] + p1.y + q1.y + bb[5];
            yv[6] = acc[i][6] + p1.z + q1.z + bb[6];
            yv[7] = acc[i][7] + p1.w + q1.w + bb[7];
            *(float4*)&g_y[(size_t)e * 128 + n0]     = make_float4(yv[0], yv[1], yv[2], yv[3]);
            *(float4*)&g_y[(size_t)e * 128 + n0 + 4] = make_float4(yv[4], yv[5], yv[6], yv[7]);
#pragma unroll
            for (int j = 0; j < 8; j++) { psum[j] += yv[j]; psq[j] += yv[j] * yv[j]; }
        }
    }

    // block reduce (over the 16 ty rows) then atomicAdd per feature
#pragma unroll
    for (int j = 0; j < 8; j++) sred[ty * 128 + n0 + j] = psum[j];
    __syncthreads();
    for (int st = 8; st > 0; st >>= 1) {
        if (ty < st) {
#pragma unroll
            for (int j = 0; j < 8; j++)
                sred[ty * 128 + n0 + j] += sred[(ty + st) * 128 + n0 + j];
        }
        __syncthreads();
    }
    if (ty == 0) {
#pragma unroll
        for (int j = 0; j < 8; j++) atomicAdd(&g_bn1s[n0 + j], sred[n0 + j]);
    }
    __syncthreads();
#pragma unroll
    for (int j = 0; j < 8; j++) sred[ty * 128 + n0 + j] = psq[j];
    __syncthreads();
    for (int st = 8; st > 0; st >>= 1) {
        if (ty < st) {
#pragma unroll
            for (int j = 0; j < 8; j++)
                sred[ty * 128 + n0 + j] += sred[(ty + st) * 128 + n0 + j];
        }
        __syncthreads();
    }
    if (ty == 0) {
#pragma unroll
        for (int j = 0; j < 8; j++) atomicAdd(&g_bn1q[n0 + j], sred[n0 + j]);
    }
}

// ---------------- k_bn1f: fold BN1 into affine a1*y + c1 ----------------
__global__ void k_bn1f(const float* __restrict__ gamma1,
                       const float* __restrict__ beta1, int E) {
    int f = threadIdx.x;  // 128
    float inv_n = 1.0f / (float)E;
    float mean = g_bn1s[f] * inv_n;
    float var  = g_bn1q[f] * inv_n - mean * mean;
    float inv  = rsqrtf(var + BN_EPS);
    float a = gamma1[f] * inv;
    g_a1[f] = a;
    g_c1[f] = beta1[f] - a * mean;
}

// ---------------- k_csr: segment boundaries from sorted self_fea_idx ----------------
__global__ void k_csr(const int* __restrict__ sidx, int E) {
    int e = blockIdx.x * blockDim.x + threadIdx.x;
    if (e >= E) return;
    int cur = sidx[e];
    int prev = (e == 0) ? -1 : sidx[e - 1];
    for (int a = prev + 1; a <= cur; a++) g_start[a] = e;
}

// ---------------- k_atom: per-atom message + segment sum (one warp per atom) --------
__global__ __launch_bounds__(256) void k_atom(int N) {
    int warp = (blockIdx.x * blockDim.x + threadIdx.x) >> 5;
    int lane = threadIdx.x & 31;
    if (warp >= N) return;
    int a = warp;
    int f1 = lane, f2 = lane + 32;

    float a1f1 = g_a1[f1],      c1f1 = g_c1[f1];
    float a1f2 = g_a1[f2],      c1f2 = g_c1[f2];
    float a1c1 = g_a1[64 + f1], c1c1 = g_c1[64 + f1];
    float a1c2 = g_a1[64 + f2], c1c2 = g_c1[64 + f2];

    float s1 = 0.f, s2 = 0.f;
    int eb = g_start[a], ee = g_start[a + 1];
    for (int e = eb; e < ee; e++) {
        const float* y = &g_y[(size_t)e * 128];
        float u1 = fmaf(a1f1, y[f1],      c1f1);
        float u2 = fmaf(a1f2, y[f2],      c1f2);
        float v1 = fmaf(a1c1, y[64 + f1], c1c1);
        float v2 = fmaf(a1c2, y[64 + f2], c1c2);
        s1 += sigmoid_f(u1) * softplus_f(v1);
        s2 += sigmoid_f(u2) * softplus_f(v2);
    }
    g_ns[(size_t)a * 64 + f1] = s1;
    g_ns[(size_t)a * 64 + f2] = s2;
}

// ---------------- k_bn2s: BN2 batch stats over nbr_sumed ----------------
__global__ __launch_bounds__(256) void k_bn2s(int N) {
    __shared__ float ss[256], sq[256];
    int f = threadIdx.x & 63;
    int r = threadIdx.x >> 6;  // 0..3
    float s = 0.f, q = 0.f;
    for (int a = blockIdx.x * 4 + r; a < N; a += gridDim.x * 4) {
        float v = g_ns[(size_t)a * 64 + f];
        s += v; q += v * v;
    }
    ss[threadIdx.x] = s; sq[threadIdx.x] = q;
    __syncthreads();
    if (r == 0) {
        s = ss[f] + ss[64 + f] + ss[128 + f] + ss[192 + f];
        q = sq[f] + sq[64 + f] + sq[128 + f] + sq[192 + f];
        atomicAdd(&g_bn2s[f], s);
        atomicAdd(&g_bn2q[f], q);
    }
}

__global__ void k_bn2f(const float* __restrict__ gamma2,
                       const float* __restrict__ beta2, int N) {
    int f = threadIdx.x;  // 64
    float inv_n = 1.0f / (float)N;
    float mean = g_bn2s[f] * inv_n;
    float var  = g_bn2q[f] * inv_n - mean * mean;
    float inv  = rsqrtf(var + BN_EPS);
    float a = gamma2[f] * inv;
    g_a2[f] = a;
    g_c2[f] = beta2[f] - a * mean;
}

// ---------------- k_final: softplus(atom + bn2(nbr_sumed)) ----------------
__global__ void k_final(const float* __restrict__ atom, float* __restrict__ out, int N) {
    int i = blockIdx.x * blockDim.x + threadIdx.x;
    if (i >= N * 64) return;
    int f = i & 63;
    float v = atom[i] + g_a2[f] * g_ns[i] + g_c2[f];
    out[i] = softplus_f(v);
}

// ---------------- launch ----------------
extern "C" void kernel_launch(void* const* d_in, const int* in_sizes, int n_in,
                              void* d_out, int out_size) {
    const float* atom   = (const float*)d_in[0];
    const float* nbr    = (const float*)d_in[1];
    const int*   sidx   = (const int*)d_in[2];
    const int*   nidx   = (const int*)d_in[3];
    const float* W      = (const float*)d_in[4];
    const float* bias   = (const float*)d_in[5];
    const float* gamma1 = (const float*)d_in[6];
    const float* beta1  = (const float*)d_in[7];
    const float* gamma2 = (const float*)d_in[8];
    const float* beta2  = (const float*)d_in[9];
    float* out = (float*)d_out;

    int N = in_sizes[0] / 64;
    int E = in_sizes[2];

    k_init<<<(N + 256) / 256, 256>>>(N, E);
    k_proj<<<(N + 63) / 64, 256>>>(atom, W,             0, N);
    k_proj<<<(N + 63) / 64, 256>>>(atom, W + 64 * 128,  1, N);
    k_edge<<<(E + 127) / 128, 256>>>(nbr, sidx, nidx, W, bias, E);
    k_bn1f<<<1, 128>>>(gamma1, beta1, E);
    k_csr<<<(E + 255) / 256, 256>>>(sidx, E);
    k_atom<<<(N + 7) / 8, 256>>>(N);
    k_bn2s<<<120, 256>>>(N);
    k_bn2f<<<1, 64>>>(gamma2, beta2, N);
    k_final<<<(N * 64 + 255) / 256, 256>>>(atom, out, N);
}

// round 5
// speedup vs baseline: 1.0025x; 1.0025x over previous
#include <cuda_runtime.h>
#include <cuda_fp16.h>
#include <cuda_bf16.h>
#include <math.h>

#define ATOMS_MAX 50000
#define EDGES_MAX 1600000
#define BN_EPS 1e-5f

// ---------------- scratch (device globals) ----------------
__device__ __align__(16) float g_Pself[ATOMS_MAX * 128];            // 25.6 MB
__device__ __align__(16) float g_Pnbr [ATOMS_MAX * 128];            // 25.6 MB
__device__ __align__(16) __half g_yh[(size_t)EDGES_MAX * 128];      // 410 MB
__device__ __align__(16) float g_ns[ATOMS_MAX * 64];                // 12.8 MB
__device__ int   g_start[ATOMS_MAX + 1];
__device__ float g_bn1s[128], g_bn1q[128], g_a1[128], g_c1[128];
__device__ float g_bn2s[64],  g_bn2q[64],  g_a2[64],  g_c2[64];

__device__ __forceinline__ float sigmoid_f(float x) { return 1.0f / (1.0f + __expf(-x)); }
__device__ __forceinline__ float softplus_f(float x) { return fmaxf(x, 0.0f) + log1pf(__expf(-fabsf(x))); }

// ---------------- helpers ----------------
__device__ __forceinline__ unsigned smem_u32(const void* p) {
    unsigned a;
    asm("{ .reg .u64 t; cvta.to.shared.u64 t, %1; cvt.u32.u64 %0, t; }" : "=r"(a) : "l"(p));
    return a;
}
__device__ __forceinline__ void bf16split(float v, unsigned short& h, unsigned short& l) {
    __nv_bfloat16 hb = __float2bfloat16(v);
    __nv_bfloat16 lb = __float2bfloat16(v - __bfloat162float(hb));
    h = __bfloat16_as_ushort(hb);
    l = __bfloat16_as_ushort(lb);
}
__device__ __forceinline__ void ldm_x4(unsigned& r0, unsigned& r1, unsigned& r2, unsigned& r3,
                                       unsigned addr) {
    asm volatile("ldmatrix.sync.aligned.m8n8.x4.shared.b16 {%0,%1,%2,%3}, [%4];"
                 : "=r"(r0), "=r"(r1), "=r"(r2), "=r"(r3) : "r"(addr));
}
__device__ __forceinline__ void ldm_x2(unsigned& r0, unsigned& r1, unsigned addr) {
    asm volatile("ldmatrix.sync.aligned.m8n8.x2.shared.b16 {%0,%1}, [%2];"
                 : "=r"(r0), "=r"(r1) : "r"(addr));
}
__device__ __forceinline__ void mma16816(float* c, const unsigned* a, unsigned b0, unsigned b1) {
    asm volatile(
        "mma.sync.aligned.m16n8k16.row.col.f32.bf16.bf16.f32 "
        "{%0,%1,%2,%3}, {%4,%5,%6,%7}, {%8,%9}, {%0,%1,%2,%3};"
        : "+f"(c[0]), "+f"(c[1]), "+f"(c[2]), "+f"(c[3])
        : "r"(a[0]), "r"(a[1]), "r"(a[2]), "r"(a[3]), "r"(b0), "r"(b1));
}

// ---------------- k_init ----------------
__global__ void k_init(int N, int E) {
    int i = blockIdx.x * blockDim.x + threadIdx.x;
    if (i < 128) { g_bn1s[i] = 0.f; g_bn1q[i] = 0.f; }
    if (i < 64)  { g_bn2s[i] = 0.f; g_bn2q[i] = 0.f; }
    if (i <= N)  g_start[i] = E;
}

// ---------------- k_proj: P = atom(N,64) @ Wp(64,128) ----------------
__global__ __launch_bounds__(256) void k_proj(const float* __restrict__ atom,
                                              const float* __restrict__ Wp,
                                              int which, int N) {
    __shared__ __align__(16) float sW[64 * 128];
    __shared__ float sA[64 * 33];
    float* __restrict__ P = which ? g_Pnbr : g_Pself;

    int tid = threadIdx.x;
    int a0 = blockIdx.x * 64;
    for (int i = tid; i < 64 * 128; i += 256) sW[i] = Wp[i];

    int tx = tid & 15, ty = tid >> 4;
    int n0 = tx * 8, m0 = ty * 4;
    float acc[4][8];
#pragma unroll
    for (int i = 0; i < 4; i++)
#pragma unroll
        for (int j = 0; j < 8; j++) acc[i][j] = 0.f;

    for (int kc = 0; kc < 64; kc += 32) {
        __syncthreads();
        for (int i = tid; i < 64 * 32; i += 256) {
            int m = i >> 5, k = i & 31;
            int a = a0 + m;
            sA[m * 33 + k] = (a < N) ? atom[(size_t)a * 64 + kc + k] : 0.f;
        }
        __syncthreads();
#pragma unroll 8
        for (int k = 0; k < 32; k++) {
            float4 b0 = *(const float4*)&sW[(kc + k) * 128 + n0];
            float4 b1 = *(const float4*)&sW[(kc + k) * 128 + n0 + 4];
            float b[8] = {b0.x, b0.y, b0.z, b0.w, b1.x, b1.y, b1.z, b1.w};
#pragma unroll
            for (int i = 0; i < 4; i++) {
                float av = sA[(m0 + i) * 33 + k];
#pragma unroll
                for (int j = 0; j < 8; j++) acc[i][j] = fmaf(av, b[j], acc[i][j]);
            }
        }
    }
#pragma unroll
    for (int i = 0; i < 4; i++) {
        int a = a0 + m0 + i;
        if (a < N) {
            *(float4*)&P[(size_t)a * 128 + n0] =
                make_float4(acc[i][0], acc[i][1], acc[i][2], acc[i][3]);
            *(float4*)&P[(size_t)a * 128 + n0 + 4] =
                make_float4(acc[i][4], acc[i][5], acc[i][6], acc[i][7]);
        }
    }
}

// ---------------- k_edge_mma: persistent HMMA edge kernel ----------------
// smem: [0..512) sidx, [512..1024) nidx, [1024..1536) bias,
// [1536..19968) A (128 rows x 72 bf16, 144B stride),
// [19968..38400) B1, [38400..56832) B2 (128 n-rows x 72 bf16 each)
#define EOFF_S  0
#define EOFF_N  512
#define EOFF_BI 1024
#define EOFF_A  1536
#define EOFF_B1 19968
#define EOFF_B2 38400
#define ESMEM   56832
#define ASTRIDE 72   // ushorts per row (144 bytes)

__global__ __launch_bounds__(256, 2) void k_edge_mma(const float* __restrict__ nbr,
                                                     const int* __restrict__ sidx,
                                                     const int* __restrict__ nidx,
                                                     const float* __restrict__ W,
                                                     const float* __restrict__ bias,
                                                     int E, int ET) {
    extern __shared__ char sm[];
    int*   sS = (int*)(sm + EOFF_S);
    int*   sN = (int*)(sm + EOFF_N);
    float* sBias = (float*)(sm + EOFF_BI);
    unsigned short* sA  = (unsigned short*)(sm + EOFF_A);
    unsigned short* sB1 = (unsigned short*)(sm + EOFF_B1);
    unsigned short* sB2 = (unsigned short*)(sm + EOFF_B2);

    int tid = threadIdx.x;
    int wid = tid >> 5;
    int lane = tid & 31;

    // build B1/B2 from W rows 128..159 (bf16 hi/lo split)
    for (int i = tid; i < 128 * 32; i += 256) {
        int n = i >> 5, k = i & 31;
        float w = W[(128 + k) * 128 + n];
        unsigned short hi, lo;
        bf16split(w, hi, lo);
        sB1[n * ASTRIDE + k]      = hi;
        sB1[n * ASTRIDE + 32 + k] = lo;
        sB2[n * ASTRIDE + k]      = lo;
        sB2[n * ASTRIDE + 32 + k] = hi;
    }
    if (tid < 128) sBias[tid] = bias[tid];

    int g = wid >> 1;      // m-group: rows g*32..g*32+31
    int h = wid & 1;       // n-half: cols h*64..h*64+63

    unsigned aBase  = smem_u32(sA);
    unsigned b1Base = smem_u32(sB1);
    unsigned b2Base = smem_u32(sB2);

    // ldmatrix lane addressing
    int arow = g * 32 + (lane & 7) + ((lane >> 3) & 1) * 8;   // + mt*16
    int acol8 = (lane >> 4);                                   // +8 cols for mats 2,3
    unsigned bRowOff = (unsigned)((h * 64 + (lane & 7)) * 144 + ((lane >> 3) & 1) * 16);

    for (int tile = blockIdx.x; tile < ET; tile += gridDim.x) {
        int e0 = tile * 128;
        __syncthreads();   // smem reuse vs previous iteration (and B build on iter 0)

        // ---- A tile: 128 edges x 32 fp32 -> [hi(0-31)|lo(32-63)] bf16 ----
        {
            int row = tid >> 1, half = tid & 1;
            int e = e0 + row;
            bool v = e < E;
            const float4* src = (const float4*)(nbr + (size_t)e * 32 + half * 16);
            unsigned short* dst = sA + row * ASTRIDE + half * 16;
#pragma unroll
            for (int j = 0; j < 4; j++) {
                float4 x = v ? src[j] : make_float4(0.f, 0.f, 0.f, 0.f);
                unsigned short h0, l0, h1, l1, h2, l2, h3, l3;
                bf16split(x.x, h0, l0); bf16split(x.y, h1, l1);
                bf16split(x.z, h2, l2); bf16split(x.w, h3, l3);
                uint2 hp, lp;
                hp.x = (unsigned)h0 | ((unsigned)h1 << 16);
                hp.y = (unsigned)h2 | ((unsigned)h3 << 16);
                lp.x = (unsigned)l0 | ((unsigned)l1 << 16);
                lp.y = (unsigned)l2 | ((unsigned)l3 << 16);
                *(uint2*)(dst + j * 4)      = hp;
                *(uint2*)(dst + 32 + j * 4) = lp;
            }
            if (tid < 128) {
                int e2 = e0 + tid;
                sS[tid] = (e2 < E) ? sidx[e2] : 0;
                sN[tid] = (e2 < E) ? nidx[e2] : 0;
            }
        }
        __syncthreads();

        // ---- MMA: acc = A[hi|lo]@B1 + A[hi|lo]@B2 (exact fp32 split) ----
        float acc[2][8][4];
#pragma unroll
        for (int mt = 0; mt < 2; mt++)
#pragma unroll
            for (int nt = 0; nt < 8; nt++)
#pragma unroll
                for (int r = 0; r < 4; r++) acc[mt][nt][r] = 0.f;

#pragma unroll
        for (int ks = 0; ks < 4; ks++) {
            unsigned a[2][4];
#pragma unroll
            for (int mt = 0; mt < 2; mt++) {
                unsigned ad = aBase + (unsigned)((arow + mt * 16) * 144 + (ks * 16 + 8 * acol8) * 2);
                ldm_x4(a[mt][0], a[mt][1], a[mt][2], a[mt][3], ad);
            }
#pragma unroll
            for (int pass = 0; pass < 2; pass++) {
                unsigned bb = (pass ? b2Base : b1Base) + bRowOff + ks * 32;
#pragma unroll
                for (int nt = 0; nt < 8; nt++) {
                    unsigned b0, b1;
                    ldm_x2(b0, b1, bb + nt * 8 * 144);
                    mma16816(acc[0][nt], a[0], b0, b1);
                    mma16816(acc[1][nt], a[1], b0, b1);
                }
            }
        }

        // ---- epilogue: acc + Pself[s] + Pnbr[n] + bias -> fp16 y ----
        int rq = lane >> 2, cq = lane & 3;
#pragma unroll
        for (int mt = 0; mt < 2; mt++) {
            int r_lo = g * 32 + mt * 16 + rq;
            int r_hi = r_lo + 8;
            int e_lo = e0 + r_lo, e_hi = e0 + r_hi;
            const float* PsL = g_Pself + (size_t)sS[r_lo] * 128;
            const float* PnL = g_Pnbr  + (size_t)sN[r_lo] * 128;
            const float* PsH = g_Pself + (size_t)sS[r_hi] * 128;
            const float* PnH = g_Pnbr  + (size_t)sN[r_hi] * 128;
            __half* yL = g_yh + (size_t)e_lo * 128;
            __half* yH = g_yh + (size_t)e_hi * 128;
            bool vL = e_lo < E, vH = e_hi < E;
#pragma unroll
            for (int nt = 0; nt < 8; nt++) {
                int c = h * 64 + nt * 8 + 2 * cq;
                float2 bb  = *(const float2*)(sBias + c);
                float2 psl = *(const float2*)(PsL + c);
                float2 pnl = *(const float2*)(PnL + c);
                float2 psh = *(const float2*)(PsH + c);
                float2 pnh = *(const float2*)(PnH + c);
                float y0 = acc[mt][nt][0] + psl.x + pnl.x + bb.x;
                float y1 = acc[mt][nt][1] + psl.y + pnl.y + bb.y;
                float y2 = acc[mt][nt][2] + psh.x + pnh.x + bb.x;
                float y3 = acc[mt][nt][3] + psh.y + pnh.y + bb.y;
                if (vL) *(__half2*)(yL + c) = __floats2half2_rn(y0, y1);
                if (vH) *(__half2*)(yH + c) = __floats2half2_rn(y2, y3);
            }
        }
    }
}

// ---------------- k_stats: BN1 sums over g_yh ----------------
__global__ __launch_bounds__(256) void k_stats(int E) {
    __shared__ float ss[256], sq[256];
    int c = threadIdx.x & 63;
    int rg = threadIdx.x >> 6;
    float s0 = 0.f, s1 = 0.f, q0 = 0.f, q1 = 0.f;
    const __half2* Y = (const __half2*)g_yh;
    for (int row = blockIdx.x * 4 + rg; row < E; row += gridDim.x * 4) {
        float2 f = __half22float2(Y[(size_t)row * 64 + c]);
        s0 += f.x; s1 += f.y;
        q0 += f.x * f.x; q1 += f.y * f.y;
    }
    ss[threadIdx.x] = s0; sq[threadIdx.x] = q0;
    __syncthreads();
    if (rg == 0) {
        float a = ss[c] + ss[64 + c] + ss[128 + c] + ss[192 + c];
        float b = sq[c] + sq[64 + c] + sq[128 + c] + sq[192 + c];
        atomicAdd(&g_bn1s[2 * c], a);
        atomicAdd(&g_bn1q[2 * c], b);
    }
    __syncthreads();
    ss[threadIdx.x] = s1; sq[threadIdx.x] = q1;
    __syncthreads();
    if (rg == 0) {
        float a = ss[c] + ss[64 + c] + ss[128 + c] + ss[192 + c];
        float b = sq[c] + sq[64 + c] + sq[128 + c] + sq[192 + c];
        atomicAdd(&g_bn1s[2 * c + 1], a);
        atomicAdd(&g_bn1q[2 * c + 1], b);
    }
}

// ---------------- k_bn1f ----------------
__global__ void k_bn1f(const float* __restrict__ gamma1,
                       const float* __restrict__ beta1, int E) {
    int f = threadIdx.x;  // 128
    float inv_n = 1.0f / (float)E;
    float mean = g_bn1s[f] * inv_n;
    float var  = g_bn1q[f] * inv_n - mean * mean;
    float inv  = rsqrtf(var + BN_EPS);
    float a = gamma1[f] * inv;
    g_a1[f] = a;
    g_c1[f] = beta1[f] - a * mean;
}

// ---------------- k_csr ----------------
__global__ void k_csr(const int* __restrict__ sidx, int E) {
    int e = blockIdx.x * blockDim.x + threadIdx.x;
    if (e >= E) return;
    int cur = sidx[e];
    int prev = (e == 0) ? -1 : sidx[e - 1];
    for (int a = prev + 1; a <= cur; a++) g_start[a] = e;
}

// ---------------- k_atom: message + segment sum (one warp per atom) ----------------
__global__ __launch_bounds__(256) void k_atom(int N) {
    int warp = (blockIdx.x * blockDim.x + threadIdx.x) >> 5;
    int lane = threadIdx.x & 31;
    if (warp >= N) return;
    int a = warp;

    float2 a1f = ((const float2*)g_a1)[lane];
    float2 c1f = ((const float2*)g_c1)[lane];
    float2 a1c = ((const float2*)g_a1)[32 + lane];
    float2 c1c = ((const float2*)g_c1)[32 + lane];

    float sx = 0.f, sy = 0.f;
    int eb = g_start[a], ee = g_start[a + 1];
    for (int e = eb; e < ee; e++) {
        const __half2* y = (const __half2*)(g_yh + (size_t)e * 128);
        float2 f = __half22float2(y[lane]);
        float2 gg = __half22float2(y[32 + lane]);
        float u0 = fmaf(a1f.x, f.x, c1f.x);
        float u1 = fmaf(a1f.y, f.y, c1f.y);
        float v0 = fmaf(a1c.x, gg.x, c1c.x);
        float v1 = fmaf(a1c.y, gg.y, c1c.y);
        sx += sigmoid_f(u0) * softplus_f(v0);
        sy += sigmoid_f(u1) * softplus_f(v1);
    }
    ((float2*)g_ns)[(size_t)a * 32 + lane] = make_float2(sx, sy);
}

// ---------------- BN2 + final ----------------
__global__ __launch_bounds__(256) void k_bn2s(int N) {
    __shared__ float ss[256], sq[256];
    int f = threadIdx.x & 63;
    int r = threadIdx.x >> 6;
    float s = 0.f, q = 0.f;
    for (int a = blockIdx.x * 4 + r; a < N; a += gridDim.x * 4) {
        float v = g_ns[(size_t)a * 64 + f];
        s += v; q += v * v;
    }
    ss[threadIdx.x] = s; sq[threadIdx.x] = q;
    __syncthreads();
    if (r == 0) {
        s = ss[f] + ss[64 + f] + ss[128 + f] + ss[192 + f];
        q = sq[f] + sq[64 + f] + sq[128 + f] + sq[192 + f];
        atomicAdd(&g_bn2s[f], s);
        atomicAdd(&g_bn2q[f], q);
    }
}

__global__ void k_bn2f(const float* __restrict__ gamma2,
                       const float* __restrict__ beta2, int N) {
    int f = threadIdx.x;  // 64
    float inv_n = 1.0f / (float)N;
    float mean = g_bn2s[f] * inv_n;
    float var  = g_bn2q[f] * inv_n - mean * mean;
    float inv  = rsqrtf(var + BN_EPS);
    float a = gamma2[f] * inv;
    g_a2[f] = a;
    g_c2[f] = beta2[f] - a * mean;
}

__global__ void k_final(const float* __restrict__ atom, float* __restrict__ out, int N) {
    int i = blockIdx.x * blockDim.x + threadIdx.x;
    if (i >= N * 64) return;
    int f = i & 63;
    float v = atom[i] + g_a2[f] * g_ns[i] + g_c2[f];
    out[i] = softplus_f(v);
}

// ---------------- launch ----------------
extern "C" void kernel_launch(void* const* d_in, const int* in_sizes, int n_in,
                              void* d_out, int out_size) {
    const float* atom   = (const float*)d_in[0];
    const float* nbr    = (const float*)d_in[1];
    const int*   sidx   = (const int*)d_in[2];
    const int*   nidx   = (const int*)d_in[3];
    const float* W      = (const float*)d_in[4];
    const float* bias   = (const float*)d_in[5];
    const float* gamma1 = (const float*)d_in[6];
    const float* beta1  = (const float*)d_in[7];
    const float* gamma2 = (const float*)d_in[8];
    const float* beta2  = (const float*)d_in[9];
    float* out = (float*)d_out;

    int N = in_sizes[0] / 64;
    int E = in_sizes[2];
    int ET = (E + 127) / 128;

    cudaFuncSetAttribute(k_edge_mma, cudaFuncAttributeMaxDynamicSharedMemorySize, ESMEM);

    k_init<<<(N + 256) / 256, 256>>>(N, E);
    k_proj<<<(N + 63) / 64, 256>>>(atom, W,            0, N);
    k_proj<<<(N + 63) / 64, 256>>>(atom, W + 64 * 128, 1, N);
    k_edge_mma<<<296, 256, ESMEM>>>(nbr, sidx, nidx, W, bias, E, ET);
    k_stats<<<1024, 256>>>(E);
    k_bn1f<<<1, 128>>>(gamma1, beta1, E);
    k_csr<<<(E + 255) / 256, 256>>>(sidx, E);
    k_atom<<<(N + 7) / 8, 256>>>(N);
    k_bn2s<<<120, 256>>>(N);
    k_bn2f<<<1, 64>>>(gamma2, beta2, N);
    k_final<<<(N * 64 + 255) / 256, 256>>>(atom, out, N);
}

// round 6
// speedup vs baseline: 1.8548x; 1.8501x over previous
#include <cuda_runtime.h>
#include <cuda_fp16.h>
#include <cuda_bf16.h>
#include <math.h>

#define ATOMS_MAX 50000
#define EDGES_MAX 1600000
#define BN_EPS 1e-5f

// ---------------- scratch (device globals) ----------------
__device__ __align__(16) float g_Pself[ATOMS_MAX * 128];            // 25.6 MB
__device__ __align__(16) float g_Pnbr [ATOMS_MAX * 128];            // 25.6 MB
__device__ __align__(16) __half g_yh[(size_t)EDGES_MAX * 128];      // 410 MB
__device__ __align__(16) float g_ns[ATOMS_MAX * 64];                // 12.8 MB
__device__ int   g_start[ATOMS_MAX + 1];
__device__ float g_bn1s[128], g_bn1q[128], g_a1[128], g_c1[128];
__device__ float g_bn2s[64],  g_bn2q[64],  g_a2[64],  g_c2[64];

__device__ __forceinline__ float sigmoid_f(float x) { return 1.0f / (1.0f + __expf(-x)); }
__device__ __forceinline__ float softplus_f(float x) { return fmaxf(x, 0.0f) + log1pf(__expf(-fabsf(x))); }

// ---------------- helpers ----------------
__device__ __forceinline__ unsigned smem_u32(const void* p) {
    unsigned a;
    asm("{ .reg .u64 t; cvta.to.shared.u64 t, %1; cvt.u32.u64 %0, t; }" : "=r"(a) : "l"(p));
    return a;
}
__device__ __forceinline__ void bf16split(float v, unsigned short& h, unsigned short& l) {
    __nv_bfloat16 hb = __float2bfloat16(v);
    __nv_bfloat16 lb = __float2bfloat16(v - __bfloat162float(hb));
    h = __bfloat16_as_ushort(hb);
    l = __bfloat16_as_ushort(lb);
}
__device__ __forceinline__ void ldm_x4(unsigned* r, unsigned addr) {
    asm volatile("ldmatrix.sync.aligned.m8n8.x4.shared.b16 {%0,%1,%2,%3}, [%4];"
                 : "=r"(r[0]), "=r"(r[1]), "=r"(r[2]), "=r"(r[3]) : "r"(addr));
}
__device__ __forceinline__ void ldm_x2(unsigned& r0, unsigned& r1, unsigned addr) {
    asm volatile("ldmatrix.sync.aligned.m8n8.x2.shared.b16 {%0,%1}, [%2];"
                 : "=r"(r0), "=r"(r1) : "r"(addr));
}
__device__ __forceinline__ void mma16816(float* c, const unsigned* a, unsigned b0, unsigned b1) {
    asm volatile(
        "mma.sync.aligned.m16n8k16.row.col.f32.bf16.bf16.f32 "
        "{%0,%1,%2,%3}, {%4,%5,%6,%7}, {%8,%9}, {%0,%1,%2,%3};"
        : "+f"(c[0]), "+f"(c[1]), "+f"(c[2]), "+f"(c[3])
        : "r"(a[0]), "r"(a[1]), "r"(a[2]), "r"(a[3]), "r"(b0), "r"(b1));
}

// ---------------- k_init ----------------
__global__ void k_init(int N, int E) {
    int i = blockIdx.x * blockDim.x + threadIdx.x;
    if (i < 128) { g_bn1s[i] = 0.f; g_bn1q[i] = 0.f; }
    if (i < 64)  { g_bn2s[i] = 0.f; g_bn2q[i] = 0.f; }
    if (i <= N)  g_start[i] = E;
}

// ---------------- k_proj: P = atom(N,64) @ Wp(64,128) ----------------
__global__ __launch_bounds__(256) void k_proj(const float* __restrict__ atom,
                                              const float* __restrict__ Wp,
                                              int which, int N) {
    __shared__ __align__(16) float sW[64 * 128];
    __shared__ float sA[64 * 33];
    float* __restrict__ P = which ? g_Pnbr : g_Pself;

    int tid = threadIdx.x;
    int a0 = blockIdx.x * 64;
    for (int i = tid; i < 64 * 128; i += 256) sW[i] = Wp[i];

    int tx = tid & 15, ty = tid >> 4;
    int n0 = tx * 8, m0 = ty * 4;
    float acc[4][8];
#pragma unroll
    for (int i = 0; i < 4; i++)
#pragma unroll
        for (int j = 0; j < 8; j++) acc[i][j] = 0.f;

    for (int kc = 0; kc < 64; kc += 32) {
        __syncthreads();
        for (int i = tid; i < 64 * 32; i += 256) {
            int m = i >> 5, k = i & 31;
            int a = a0 + m;
            sA[m * 33 + k] = (a < N) ? atom[(size_t)a * 64 + kc + k] : 0.f;
        }
        __syncthreads();
#pragma unroll 8
        for (int k = 0; k < 32; k++) {
            float4 b0 = *(const float4*)&sW[(kc + k) * 128 + n0];
            float4 b1 = *(const float4*)&sW[(kc + k) * 128 + n0 + 4];
            float b[8] = {b0.x, b0.y, b0.z, b0.w, b1.x, b1.y, b1.z, b1.w};
#pragma unroll
            for (int i = 0; i < 4; i++) {
                float av = sA[(m0 + i) * 33 + k];
#pragma unroll
                for (int j = 0; j < 8; j++) acc[i][j] = fmaf(av, b[j], acc[i][j]);
            }
        }
    }
#pragma unroll
    for (int i = 0; i < 4; i++) {
        int a = a0 + m0 + i;
        if (a < N) {
            *(float4*)&P[(size_t)a * 128 + n0] =
                make_float4(acc[i][0], acc[i][1], acc[i][2], acc[i][3]);
            *(float4*)&P[(size_t)a * 128 + n0 + 4] =
                make_float4(acc[i][4], acc[i][5], acc[i][6], acc[i][7]);
        }
    }
}

// ---------------- k_edge_mma v3: persistent HMMA + smem-staged epilogue ---------
// smem: [0..512) sidx, [512..1024) nidx, [1536..19968) A (128x72 bf16, 144B),
// [19968..38400) B1 (128x72 bf16), [38400..106240) Y (128 x 132 fp32, 528B)
#define EOFF_S  0
#define EOFF_N  512
#define EOFF_A  1536
#define EOFF_B  19968
#define EOFF_Y  38400
#define ESMEM   (38400 + 128 * 132 * 4)    // 105984
#define ASTRIDE 72     // ushorts per row (144 bytes)
#define YSTRIDE 132    // floats per row (528 bytes)

__global__ __launch_bounds__(256, 2) void k_edge_mma(const float* __restrict__ nbr,
                                                     const int* __restrict__ sidx,
                                                     const int* __restrict__ nidx,
                                                     const float* __restrict__ W,
                                                     const float* __restrict__ bias,
                                                     int E, int ET) {
    extern __shared__ char sm[];
    int*   sS = (int*)(sm + EOFF_S);
    int*   sN = (int*)(sm + EOFF_N);
    unsigned short* sA = (unsigned short*)(sm + EOFF_A);
    unsigned short* sB = (unsigned short*)(sm + EOFF_B);
    float* sY = (float*)(sm + EOFF_Y);

    int tid = threadIdx.x;
    int wid = tid >> 5;
    int lane = tid & 31;

    // build B1 = [Whi(k0..31) | Wlo(k0..31)] per output row n (bf16 hi/lo split)
    for (int i = tid; i < 128 * 32; i += 256) {
        int n = i >> 5, k = i & 31;
        float w = W[(128 + k) * 128 + n];
        unsigned short hi, lo;
        bf16split(w, hi, lo);
        sB[n * ASTRIDE + k]      = hi;
        sB[n * ASTRIDE + 32 + k] = lo;
    }
    float4 biasv = ((const float4*)bias)[lane];   // cols lane*4..lane*4+3

    int g = wid >> 1;      // m-group: rows g*32..g*32+31
    int h = wid & 1;       // n-half: cols h*64..h*64+63

    unsigned aBase = smem_u32(sA);
    unsigned bBase = smem_u32(sB);

    int arow = g * 32 + (lane & 7) + ((lane >> 3) & 1) * 8;
    int acol8 = (lane >> 4);
    unsigned bRowOff = (unsigned)((h * 64 + (lane & 7)) * 144 + ((lane >> 3) & 1) * 16);

    // persistent BN1 stat accumulators (cols lane*4..lane*4+3)
    float4 st = make_float4(0.f, 0.f, 0.f, 0.f);
    float4 sq = make_float4(0.f, 0.f, 0.f, 0.f);

    for (int tile = blockIdx.x; tile < ET; tile += gridDim.x) {
        int e0 = tile * 128;
        __syncthreads();   // smem reuse vs previous epilogue / B build

        // ---- A tile: 128 edges x 32 fp32 -> [hi(0-31)|lo(32-63)] bf16 ----
        {
            int row = tid >> 1, half = tid & 1;
            int e = e0 + row;
            bool v = e < E;
            const float4* src = (const float4*)(nbr + (size_t)e * 32 + half * 16);
            unsigned short* dst = sA + row * ASTRIDE + half * 16;
#pragma unroll
            for (int j = 0; j < 4; j++) {
                float4 x = v ? src[j] : make_float4(0.f, 0.f, 0.f, 0.f);
                unsigned short h0, l0, h1, l1, h2, l2, h3, l3;
                bf16split(x.x, h0, l0); bf16split(x.y, h1, l1);
                bf16split(x.z, h2, l2); bf16split(x.w, h3, l3);
                uint2 hp, lp;
                hp.x = (unsigned)h0 | ((unsigned)h1 << 16);
                hp.y = (unsigned)h2 | ((unsigned)h3 << 16);
                lp.x = (unsigned)l0 | ((unsigned)l1 << 16);
                lp.y = (unsigned)l2 | ((unsigned)l3 << 16);
                *(uint2*)(dst + j * 4)      = hp;
                *(uint2*)(dst + 32 + j * 4) = lp;
            }
            if (tid < 128) {
                int e2 = e0 + tid;
                sS[tid] = (e2 < E) ? sidx[e2] : 0;
                sN[tid] = (e2 < E) ? nidx[e2] : 0;
            }
        }
        __syncthreads();

        // ---- MMA: pass1 Σ A_j·B_j + pass2 Σ A_{j^2}·B_j  (exact bf16 split) ----
        float acc[2][8][4];
#pragma unroll
        for (int mt = 0; mt < 2; mt++)
#pragma unroll
            for (int nt = 0; nt < 8; nt++)
#pragma unroll
                for (int r = 0; r < 4; r++) acc[mt][nt][r] = 0.f;

#pragma unroll
        for (int j = 0; j < 4; j++) {
            unsigned a1f[2][4], a2f[2][4];
#pragma unroll
            for (int mt = 0; mt < 2; mt++) {
                unsigned base = aBase + (unsigned)((arow + mt * 16) * 144);
                ldm_x4(a1f[mt], base + (unsigned)((j * 16 + 8 * acol8) * 2));
                ldm_x4(a2f[mt], base + (unsigned)(((j ^ 2) * 16 + 8 * acol8) * 2));
            }
            unsigned bf[8][2];
#pragma unroll
            for (int nt = 0; nt < 8; nt++)
                ldm_x2(bf[nt][0], bf[nt][1], bBase + bRowOff + (unsigned)(j * 32 + nt * 8 * 144));
#pragma unroll
            for (int nt = 0; nt < 8; nt++) {
                mma16816(acc[0][nt], a1f[0], bf[nt][0], bf[nt][1]);
                mma16816(acc[1][nt], a1f[1], bf[nt][0], bf[nt][1]);
                mma16816(acc[0][nt], a2f[0], bf[nt][0], bf[nt][1]);
                mma16816(acc[1][nt], a2f[1], bf[nt][0], bf[nt][1]);
            }
        }

        // ---- stage acc -> sY (padded stride kills most conflicts) ----
        {
            int rq = lane >> 2, cq = lane & 3;
#pragma unroll
            for (int mt = 0; mt < 2; mt++) {
                int r0 = g * 32 + mt * 16 + rq;
#pragma unroll
                for (int nt = 0; nt < 8; nt++) {
                    int c = h * 64 + nt * 8 + 2 * cq;
                    *(float2*)&sY[r0 * YSTRIDE + c]       = make_float2(acc[mt][nt][0], acc[mt][nt][1]);
                    *(float2*)&sY[(r0 + 8) * YSTRIDE + c] = make_float2(acc[mt][nt][2], acc[mt][nt][3]);
                }
            }
        }
        __syncthreads();

        // ---- row-wise epilogue: coalesced P gathers + fp16 store + BN1 stats ----
#pragma unroll 2
        for (int i = 0; i < 16; i++) {
            int row = wid * 16 + i;
            int e = e0 + row;
            if (e >= E) continue;
            int s = sS[row], n = sN[row];
            float4 a4 = *(const float4*)&sY[row * YSTRIDE + lane * 4];
            float4 ps = ((const float4*)(g_Pself + (size_t)s * 128))[lane];
            float4 pn = ((const float4*)(g_Pnbr + (size_t)n * 128))[lane];
            float y0 = a4.x + ps.x + pn.x + biasv.x;
            float y1 = a4.y + ps.y + pn.y + biasv.y;
            float y2 = a4.z + ps.z + pn.z + biasv.z;
            float y3 = a4.w + ps.w + pn.w + biasv.w;
            st.x += y0; st.y += y1; st.z += y2; st.w += y3;
            sq.x += y0 * y0; sq.y += y1 * y1; sq.z += y2 * y2; sq.w += y3 * y3;
            __half2 p01 = __floats2half2_rn(y0, y1);
            __half2 p23 = __floats2half2_rn(y2, y3);
            uint2 u;
            u.x = *(unsigned*)&p01;
            u.y = *(unsigned*)&p23;
            *(uint2*)(g_yh + (size_t)e * 128 + lane * 4) = u;
        }
    }

    // ---- BN1 stats: cross-warp reduce in smem, one atomicAdd per col per CTA ----
    __syncthreads();
    *(float4*)&sY[wid * 128 + lane * 4] = st;
    *(float4*)&sY[1024 + wid * 128 + lane * 4] = sq;
    __syncthreads();
    if (tid < 128) {
        float a = 0.f, b = 0.f;
#pragma unroll
        for (int w = 0; w < 8; w++) {
            a += sY[w * 128 + tid];
            b += sY[1024 + w * 128 + tid];
        }
        atomicAdd(&g_bn1s[tid], a);
        atomicAdd(&g_bn1q[tid], b);
    }
}

// ---------------- k_bn1f ----------------
__global__ void k_bn1f(const float* __restrict__ gamma1,
                       const float* __restrict__ beta1, int E) {
    int f = threadIdx.x;  // 128
    float inv_n = 1.0f / (float)E;
    float mean = g_bn1s[f] * inv_n;
    float var  = g_bn1q[f] * inv_n - mean * mean;
    float inv  = rsqrtf(var + BN_EPS);
    float a = gamma1[f] * inv;
    g_a1[f] = a;
    g_c1[f] = beta1[f] - a * mean;
}

// ---------------- k_csr ----------------
__global__ void k_csr(const int* __restrict__ sidx, int E) {
    int e = blockIdx.x * blockDim.x + threadIdx.x;
    if (e >= E) return;
    int cur = sidx[e];
    int prev = (e == 0) ? -1 : sidx[e - 1];
    for (int a = prev + 1; a <= cur; a++) g_start[a] = e;
}

// ---------------- k_atom: message + segment sum (warp/atom, 2x unroll) ----------
__global__ __launch_bounds__(256) void k_atom(int N) {
    int warp = (blockIdx.x * blockDim.x + threadIdx.x) >> 5;
    int lane = threadIdx.x & 31;
    if (warp >= N) return;
    int a = warp;

    float2 a1f = ((const float2*)g_a1)[lane];
    float2 c1f = ((const float2*)g_c1)[lane];
    float2 a1c = ((const float2*)g_a1)[32 + lane];
    float2 c1c = ((const float2*)g_c1)[32 + lane];

    float sx = 0.f, sy = 0.f;
    int eb = g_start[a], ee = g_start[a + 1];
    int e = eb;
    for (; e + 2 <= ee; e += 2) {
        const __half2* y0 = (const __half2*)(g_yh + (size_t)e * 128);
        const __half2* y1 = (const __half2*)(g_yh + (size_t)(e + 1) * 128);
        __half2 hf0 = y0[lane], hg0 = y0[32 + lane];
        __half2 hf1 = y1[lane], hg1 = y1[32 + lane];
        float2 F0 = __half22float2(hf0), G0 = __half22float2(hg0);
        float2 F1 = __half22float2(hf1), G1 = __half22float2(hg1);
        sx += sigmoid_f(fmaf(a1f.x, F0.x, c1f.x)) * softplus_f(fmaf(a1c.x, G0.x, c1c.x));
        sy += sigmoid_f(fmaf(a1f.y, F0.y, c1f.y)) * softplus_f(fmaf(a1c.y, G0.y, c1c.y));
        sx += sigmoid_f(fmaf(a1f.x, F1.x, c1f.x)) * softplus_f(fmaf(a1c.x, G1.x, c1c.x));
        sy += sigmoid_f(fmaf(a1f.y, F1.y, c1f.y)) * softplus_f(fmaf(a1c.y, G1.y, c1c.y));
    }
    if (e < ee) {
        const __half2* y0 = (const __half2*)(g_yh + (size_t)e * 128);
        float2 F0 = __half22float2(y0[lane]), G0 = __half22float2(y0[32 + lane]);
        sx += sigmoid_f(fmaf(a1f.x, F0.x, c1f.x)) * softplus_f(fmaf(a1c.x, G0.x, c1c.x));
        sy += sigmoid_f(fmaf(a1f.y, F0.y, c1f.y)) * softplus_f(fmaf(a1c.y, G0.y, c1c.y));
    }
    ((float2*)g_ns)[(size_t)a * 32 + lane] = make_float2(sx, sy);
}

// ---------------- BN2 + final ----------------
__global__ __launch_bounds__(256) void k_bn2s(int N) {
    __shared__ float ss[256], sq2[256];
    int f = threadIdx.x & 63;
    int r = threadIdx.x >> 6;
    float s = 0.f, q = 0.f;
    for (int a = blockIdx.x * 4 + r; a < N; a += gridDim.x * 4) {
        float v = g_ns[(size_t)a * 64 + f];
        s += v; q += v * v;
    }
    ss[threadIdx.x] = s; sq2[threadIdx.x] = q;
    __syncthreads();
    if (r == 0) {
        s = ss[f] + ss[64 + f] + ss[128 + f] + ss[192 + f];
        q = sq2[f] + sq2[64 + f] + sq2[128 + f] + sq2[192 + f];
        atomicAdd(&g_bn2s[f], s);
        atomicAdd(&g_bn2q[f], q);
    }
}

__global__ void k_bn2f(const float* __restrict__ gamma2,
                       const float* __restrict__ beta2, int N) {
    int f = threadIdx.x;  // 64
    float inv_n = 1.0f / (float)N;
    float mean = g_bn2s[f] * inv_n;
    float var  = g_bn2q[f] * inv_n - mean * mean;
    float inv  = rsqrtf(var + BN_EPS);
    float a = gamma2[f] * inv;
    g_a2[f] = a;
    g_c2[f] = beta2[f] - a * mean;
}

__global__ void k_final(const float* __restrict__ atom, float* __restrict__ out, int N) {
    int i = blockIdx.x * blockDim.x + threadIdx.x;
    if (i >= N * 64) return;
    int f = i & 63;
    float v = atom[i] + g_a2[f] * g_ns[i] + g_c2[f];
    out[i] = softplus_f(v);
}

// ---------------- launch ----------------
extern "C" void kernel_launch(void* const* d_in, const int* in_sizes, int n_in,
                              void* d_out, int out_size) {
    const float* atom   = (const float*)d_in[0];
    const float* nbr    = (const float*)d_in[1];
    const int*   sidx   = (const int*)d_in[2];
    const int*   nidx   = (const int*)d_in[3];
    const float* W      = (const float*)d_in[4];
    const float* bias   = (const float*)d_in[5];
    const float* gamma1 = (const float*)d_in[6];
    const float* beta1  = (const float*)d_in[7];
    const float* gamma2 = (const float*)d_in[8];
    const float* beta2  = (const float*)d_in[9];
    float* out = (float*)d_out;

    int N = in_sizes[0] / 64;
    int E = in_sizes[2];
    int ET = (E + 127) / 128;

    cudaFuncSetAttribute(k_edge_mma, cudaFuncAttributeMaxDynamicSharedMemorySize, ESMEM);

    k_init<<<(N + 256) / 256, 256>>>(N, E);
    k_proj<<<(N + 63) / 64, 256>>>(atom, W,            0, N);
    k_proj<<<(N + 63) / 64, 256>>>(atom, W + 64 * 128, 1, N);
    k_edge_mma<<<296, 256, ESMEM>>>(nbr, sidx, nidx, W, bias, E, ET);
    k_bn1f<<<1, 128>>>(gamma1, beta1, E);
    k_csr<<<(E + 255) / 256, 256>>>(sidx, E);
    k_atom<<<(N + 7) / 8, 256>>>(N);
    k_bn2s<<<120, 256>>>(N);
    k_bn2f<<<1, 64>>>(gamma2, beta2, N);
    k_final<<<(N * 64 + 255) / 256, 256>>>(atom, out, N);
}

// round 7
// speedup vs baseline: 1.8728x; 1.0097x over previous
#include <cuda_runtime.h>
#include <cuda_fp16.h>
#include <cuda_bf16.h>
#include <math.h>

#define ATOMS_MAX 50000
#define EDGES_MAX 1600000
#define BN_EPS 1e-5f

// ---------------- scratch (device globals) ----------------
__device__ __align__(16) float g_Pself[ATOMS_MAX * 128];            // 25.6 MB
__device__ __align__(16) float g_Pnbr [ATOMS_MAX * 128];            // 25.6 MB
__device__ __align__(16) __half g_yh[(size_t)EDGES_MAX * 128];      // 410 MB
__device__ __align__(16) float g_ns[ATOMS_MAX * 64];                // 12.8 MB
__device__ int   g_start[ATOMS_MAX + 1];
__device__ float g_bn1s[128], g_bn1q[128], g_a1[128], g_c1[128];
__device__ float g_bn2s[64],  g_bn2q[64],  g_a2[64],  g_c2[64];

__device__ __forceinline__ float sigmoid_f(float x) { return 1.0f / (1.0f + __expf(-x)); }
__device__ __forceinline__ float softplus_f(float x) { return fmaxf(x, 0.0f) + log1pf(__expf(-fabsf(x))); }

// ---------------- helpers ----------------
__device__ __forceinline__ unsigned smem_u32(const void* p) {
    unsigned a;
    asm("{ .reg .u64 t; cvta.to.shared.u64 t, %1; cvt.u32.u64 %0, t; }" : "=r"(a) : "l"(p));
    return a;
}
__device__ __forceinline__ void bf16split(float v, unsigned short& h, unsigned short& l) {
    __nv_bfloat16 hb = __float2bfloat16(v);
    __nv_bfloat16 lb = __float2bfloat16(v - __bfloat162float(hb));
    h = __bfloat16_as_ushort(hb);
    l = __bfloat16_as_ushort(lb);
}
__device__ __forceinline__ void ldm_x4(unsigned* r, unsigned addr) {
    asm volatile("ldmatrix.sync.aligned.m8n8.x4.shared.b16 {%0,%1,%2,%3}, [%4];"
                 : "=r"(r[0]), "=r"(r[1]), "=r"(r[2]), "=r"(r[3]) : "r"(addr));
}
__device__ __forceinline__ void ldm_x2(unsigned& r0, unsigned& r1, unsigned addr) {
    asm volatile("ldmatrix.sync.aligned.m8n8.x2.shared.b16 {%0,%1}, [%2];"
                 : "=r"(r0), "=r"(r1) : "r"(addr));
}
__device__ __forceinline__ void mma16816(float* c, const unsigned* a, unsigned b0, unsigned b1) {
    asm volatile(
        "mma.sync.aligned.m16n8k16.row.col.f32.bf16.bf16.f32 "
        "{%0,%1,%2,%3}, {%4,%5,%6,%7}, {%8,%9}, {%0,%1,%2,%3};"
        : "+f"(c[0]), "+f"(c[1]), "+f"(c[2]), "+f"(c[3])
        : "r"(a[0]), "r"(a[1]), "r"(a[2]), "r"(a[3]), "r"(b0), "r"(b1));
}
__device__ __forceinline__ void cp_async16(unsigned dst, const void* src) {
    asm volatile("cp.async.cg.shared.global [%0], [%1], 16;" :: "r"(dst), "l"(src));
}
#define CP_COMMIT() asm volatile("cp.async.commit_group;" ::: "memory")
#define CP_WAIT0()  asm volatile("cp.async.wait_group 0;" ::: "memory")

// ---------------- k_init ----------------
__global__ void k_init(int N, int E) {
    int i = blockIdx.x * blockDim.x + threadIdx.x;
    if (i < 128) { g_bn1s[i] = 0.f; g_bn1q[i] = 0.f; }
    if (i < 64)  { g_bn2s[i] = 0.f; g_bn2q[i] = 0.f; }
    if (i <= N)  g_start[i] = E;
}

// ---------------- k_proj: P = atom(N,64) @ Wp(64,128) ----------------
__global__ __launch_bounds__(256) void k_proj(const float* __restrict__ atom,
                                              const float* __restrict__ Wp,
                                              int which, int N) {
    __shared__ __align__(16) float sW[64 * 128];
    __shared__ float sA[64 * 33];
    float* __restrict__ P = which ? g_Pnbr : g_Pself;

    int tid = threadIdx.x;
    int a0 = blockIdx.x * 64;
    for (int i = tid; i < 64 * 128; i += 256) sW[i] = Wp[i];

    int tx = tid & 15, ty = tid >> 4;
    int n0 = tx * 8, m0 = ty * 4;
    float acc[4][8];
#pragma unroll
    for (int i = 0; i < 4; i++)
#pragma unroll
        for (int j = 0; j < 8; j++) acc[i][j] = 0.f;

    for (int kc = 0; kc < 64; kc += 32) {
        __syncthreads();
        for (int i = tid; i < 64 * 32; i += 256) {
            int m = i >> 5, k = i & 31;
            int a = a0 + m;
            sA[m * 33 + k] = (a < N) ? atom[(size_t)a * 64 + kc + k] : 0.f;
        }
        __syncthreads();
#pragma unroll 8
        for (int k = 0; k < 32; k++) {
            float4 b0 = *(const float4*)&sW[(kc + k) * 128 + n0];
            float4 b1 = *(const float4*)&sW[(kc + k) * 128 + n0 + 4];
            float b[8] = {b0.x, b0.y, b0.z, b0.w, b1.x, b1.y, b1.z, b1.w};
#pragma unroll
            for (int i = 0; i < 4; i++) {
                float av = sA[(m0 + i) * 33 + k];
#pragma unroll
                for (int j = 0; j < 8; j++) acc[i][j] = fmaf(av, b[j], acc[i][j]);
            }
        }
    }
#pragma unroll
    for (int i = 0; i < 4; i++) {
        int a = a0 + m0 + i;
        if (a < N) {
            *(float4*)&P[(size_t)a * 128 + n0] =
                make_float4(acc[i][0], acc[i][1], acc[i][2], acc[i][3]);
            *(float4*)&P[(size_t)a * 128 + n0 + 4] =
                make_float4(acc[i][4], acc[i][5], acc[i][6], acc[i][7]);
        }
    }
}

// ---------------- k_edge_mma v4: cp.async pipelined HMMA ----------------
// smem: [0..512) sidx, [512..1024) nidx, [1024..1536) pad,
// [1536..19968)  sRaw (128 x 36 fp32, 144B stride)
// [19968..38400) sA   (128 x 72 bf16, 144B)
// [38400..56832) sB   (128 x 72 bf16, 144B)
// [56832..90624) sY   (64 x 132 fp32, 528B)
#define EOFF_S   0
#define EOFF_N   512
#define EOFF_RAW 1536
#define EOFF_A   19968
#define EOFF_B   38400
#define EOFF_Y   56832
#define ESMEM    (56832 + 64 * 132 * 4)    // 90624
#define ASTRIDE  72     // ushorts per row (144 bytes)
#define RSTRIDE  36     // floats per row (144 bytes)
#define YSTRIDE  132    // floats per row (528 bytes)

__global__ __launch_bounds__(256, 2) void k_edge_mma(const float* __restrict__ nbr,
                                                     const int* __restrict__ sidx,
                                                     const int* __restrict__ nidx,
                                                     const float* __restrict__ W,
                                                     const float* __restrict__ bias,
                                                     int E, int ET) {
    extern __shared__ char sm[];
    int*   sS = (int*)(sm + EOFF_S);
    int*   sN = (int*)(sm + EOFF_N);
    float* sRaw = (float*)(sm + EOFF_RAW);
    unsigned short* sA = (unsigned short*)(sm + EOFF_A);
    unsigned short* sB = (unsigned short*)(sm + EOFF_B);
    float* sY = (float*)(sm + EOFF_Y);

    int tid = threadIdx.x;
    int wid = tid >> 5;
    int lane = tid & 31;

    // build B = [Whi(k0..31) | Wlo(k0..31)] per output row n (bf16 hi/lo split)
    for (int i = tid; i < 128 * 32; i += 256) {
        int n = i >> 5, k = i & 31;
        float w = W[(128 + k) * 128 + n];
        unsigned short hi, lo;
        bf16split(w, hi, lo);
        sB[n * ASTRIDE + k]      = hi;
        sB[n * ASTRIDE + 32 + k] = lo;
    }
    float4 biasv = ((const float4*)bias)[lane];   // cols lane*4..lane*4+3

    int g = wid >> 1;      // m-group: rows g*32..g*32+31
    int h = wid & 1;       // n-half: cols h*64..h*64+63

    unsigned aBase = smem_u32(sA);
    unsigned bBase = smem_u32(sB);
    unsigned rawBase = smem_u32(sRaw);

    int arow = g * 32 + (lane & 7) + ((lane >> 3) & 1) * 8;
    int acol8 = (lane >> 4);
    unsigned bRowOff = (unsigned)((h * 64 + (lane & 7)) * 144 + ((lane >> 3) & 1) * 16);

    // BN1 stat accumulators (cols lane*4..lane*4+3)
    float4 st = make_float4(0.f, 0.f, 0.f, 0.f);
    float4 sq = make_float4(0.f, 0.f, 0.f, 0.f);

    // ---- prefetch A(tile0) into sRaw ----
    {
        int tile = blockIdx.x;
        int e0 = tile * 128;
#pragma unroll
        for (int j = 0; j < 4; j++) {
            int chunk = j * 256 + tid;       // 0..1023
            int row = chunk >> 3;
            int c = (chunk & 7) * 4;
            int e = e0 + row;
            if (e >= E || tile >= ET) e = 0;
            cp_async16(rawBase + (unsigned)((row * RSTRIDE + c) * 4),
                       nbr + (size_t)e * 32 + c);
        }
        CP_COMMIT();
    }

    for (int tile = blockIdx.x; tile < ET; tile += gridDim.x) {
        int e0 = tile * 128;
        CP_WAIT0();
        __syncthreads();   // raw ready; sA/sY free from previous iteration

        // ---- split: sRaw fp32 -> sA [hi(0-31)|lo(32-63)] bf16 ----
        {
            int row = tid >> 1, half = tid & 1;
            const float* rp = sRaw + row * RSTRIDE + half * 16;
            unsigned short* dst = sA + row * ASTRIDE + half * 16;
#pragma unroll
            for (int j = 0; j < 4; j++) {
                float4 x = *(const float4*)(rp + j * 4);
                unsigned short h0, l0, h1, l1, h2, l2, h3, l3;
                bf16split(x.x, h0, l0); bf16split(x.y, h1, l1);
                bf16split(x.z, h2, l2); bf16split(x.w, h3, l3);
                uint2 hp, lp;
                hp.x = (unsigned)h0 | ((unsigned)h1 << 16);
                hp.y = (unsigned)h2 | ((unsigned)h3 << 16);
                lp.x = (unsigned)l0 | ((unsigned)l1 << 16);
                lp.y = (unsigned)l2 | ((unsigned)l3 << 16);
                *(uint2*)(dst + j * 4)      = hp;
                *(uint2*)(dst + 32 + j * 4) = lp;
            }
            if (tid < 128) {
                int e2 = e0 + tid;
                sS[tid] = (e2 < E) ? sidx[e2] : 0;
                sN[tid] = (e2 < E) ? nidx[e2] : 0;
            }
        }
        __syncthreads();   // sA ready; sRaw free

        // ---- prefetch A(next tile) — overlaps MMA + epilogue ----
        {
            int nt2 = tile + gridDim.x;
            int ne0 = nt2 * 128;
#pragma unroll
            for (int j = 0; j < 4; j++) {
                int chunk = j * 256 + tid;
                int row = chunk >> 3;
                int c = (chunk & 7) * 4;
                int e = ne0 + row;
                if (e >= E || nt2 >= ET) e = 0;
                cp_async16(rawBase + (unsigned)((row * RSTRIDE + c) * 4),
                           nbr + (size_t)e * 32 + c);
            }
            CP_COMMIT();
        }

        // ---- MMA: pass1 Σ A_j·B_j + pass2 Σ A_{j^2}·B_j (exact bf16 split) ----
        float acc[2][8][4];
#pragma unroll
        for (int mt = 0; mt < 2; mt++)
#pragma unroll
            for (int nt = 0; nt < 8; nt++)
#pragma unroll
                for (int r = 0; r < 4; r++) acc[mt][nt][r] = 0.f;

#pragma unroll
        for (int j = 0; j < 4; j++) {
            unsigned a1f[2][4], a2f[2][4];
#pragma unroll
            for (int mt = 0; mt < 2; mt++) {
                unsigned base = aBase + (unsigned)((arow + mt * 16) * 144);
                ldm_x4(a1f[mt], base + (unsigned)((j * 16 + 8 * acol8) * 2));
                ldm_x4(a2f[mt], base + (unsigned)(((j ^ 2) * 16 + 8 * acol8) * 2));
            }
            unsigned bf[8][2];
#pragma unroll
            for (int nt = 0; nt < 8; nt++)
                ldm_x2(bf[nt][0], bf[nt][1], bBase + bRowOff + (unsigned)(j * 32 + nt * 8 * 144));
#pragma unroll
            for (int nt = 0; nt < 8; nt++) {
                mma16816(acc[0][nt], a1f[0], bf[nt][0], bf[nt][1]);
                mma16816(acc[1][nt], a1f[1], bf[nt][0], bf[nt][1]);
                mma16816(acc[0][nt], a2f[0], bf[nt][0], bf[nt][1]);
                mma16816(acc[1][nt], a2f[1], bf[nt][0], bf[nt][1]);
            }
        }

        // ---- two epilogue waves of 64 rows through the 64-row sY buffer ----
#pragma unroll
        for (int wave = 0; wave < 2; wave++) {
            // stage: groups {wave*2, wave*2+1} i.e. warps with g in that set
            if (g == wave * 2 || g == wave * 2 + 1) {
                int rq = lane >> 2, cq = lane & 3;
                int gl = g - wave * 2;   // 0 or 1 within wave
#pragma unroll
                for (int mt = 0; mt < 2; mt++) {
                    int r0 = gl * 32 + mt * 16 + rq;   // sY row 0..63
#pragma unroll
                    for (int nt = 0; nt < 8; nt++) {
                        int c = h * 64 + nt * 8 + 2 * cq;
                        *(float2*)&sY[r0 * YSTRIDE + c]       = make_float2(acc[mt][nt][0], acc[mt][nt][1]);
                        *(float2*)&sY[(r0 + 8) * YSTRIDE + c] = make_float2(acc[mt][nt][2], acc[mt][nt][3]);
                    }
                }
            }
            __syncthreads();
            // epilogue: 64 rows, warp w -> rows w*8..w*8+7
#pragma unroll 2
            for (int i = 0; i < 8; i++) {
                int yrow = wid * 8 + i;            // 0..63
                int row = wave * 64 + yrow;        // tile row
                int e = e0 + row;
                if (e >= E) continue;
                int s = sS[row], n = sN[row];
                float4 a4 = *(const float4*)&sY[yrow * YSTRIDE + lane * 4];
                float4 ps = ((const float4*)(g_Pself + (size_t)s * 128))[lane];
                float4 pn = ((const float4*)(g_Pnbr + (size_t)n * 128))[lane];
                float y0 = a4.x + ps.x + pn.x + biasv.x;
                float y1 = a4.y + ps.y + pn.y + biasv.y;
                float y2 = a4.z + ps.z + pn.z + biasv.z;
                float y3 = a4.w + ps.w + pn.w + biasv.w;
                st.x += y0; st.y += y1; st.z += y2; st.w += y3;
                sq.x += y0 * y0; sq.y += y1 * y1; sq.z += y2 * y2; sq.w += y3 * y3;
                __half2 p01 = __floats2half2_rn(y0, y1);
                __half2 p23 = __floats2half2_rn(y2, y3);
                uint2 u;
                u.x = *(unsigned*)&p01;
                u.y = *(unsigned*)&p23;
                __stcs((uint2*)(g_yh + (size_t)e * 128 + lane * 4), u);
            }
            __syncthreads();
        }
    }

    // ---- BN1 stats: cross-warp reduce in smem, one atomicAdd per col per CTA ----
    __syncthreads();
    *(float4*)&sY[wid * 128 + lane * 4] = st;
    *(float4*)&sY[1024 + wid * 128 + lane * 4] = sq;
    __syncthreads();
    if (tid < 128) {
        float a = 0.f, b = 0.f;
#pragma unroll
        for (int w = 0; w < 8; w++) {
            a += sY[w * 128 + tid];
            b += sY[1024 + w * 128 + tid];
        }
        atomicAdd(&g_bn1s[tid], a);
        atomicAdd(&g_bn1q[tid], b);
    }
}

// ---------------- k_bn1f ----------------
__global__ void k_bn1f(const float* __restrict__ gamma1,
                       const float* __restrict__ beta1, int E) {
    int f = threadIdx.x;  // 128
    float inv_n = 1.0f / (float)E;
    float mean = g_bn1s[f] * inv_n;
    float var  = g_bn1q[f] * inv_n - mean * mean;
    float inv  = rsqrtf(var + BN_EPS);
    float a = gamma1[f] * inv;
    g_a1[f] = a;
    g_c1[f] = beta1[f] - a * mean;
}

// ---------------- k_csr ----------------
__global__ void k_csr(const int* __restrict__ sidx, int E) {
    int e = blockIdx.x * blockDim.x + threadIdx.x;
    if (e >= E) return;
    int cur = sidx[e];
    int prev = (e == 0) ? -1 : sidx[e - 1];
    for (int a = prev + 1; a <= cur; a++) g_start[a] = e;
}

// ---------------- k_atom: message + segment sum (warp/atom, 4x unroll) ----------
__global__ __launch_bounds__(256) void k_atom(int N) {
    int warp = (blockIdx.x * blockDim.x + threadIdx.x) >> 5;
    int lane = threadIdx.x & 31;
    if (warp >= N) return;
    int a = warp;

    float2 a1f = ((const float2*)g_a1)[lane];
    float2 c1f = ((const float2*)g_c1)[lane];
    float2 a1c = ((const float2*)g_a1)[32 + lane];
    float2 c1c = ((const float2*)g_c1)[32 + lane];

    float sx = 0.f, sy = 0.f;
    int eb = g_start[a], ee = g_start[a + 1];
    int e = eb;
    for (; e + 4 <= ee; e += 4) {
        float2 F[4], G[4];
#pragma unroll
        for (int q = 0; q < 4; q++) {
            const __half2* y = (const __half2*)(g_yh + (size_t)(e + q) * 128);
            __half2 hf = __ldcs(&y[lane]);
            __half2 hg = __ldcs(&y[32 + lane]);
            F[q] = __half22float2(hf);
            G[q] = __half22float2(hg);
        }
#pragma unroll
        for (int q = 0; q < 4; q++) {
            sx += sigmoid_f(fmaf(a1f.x, F[q].x, c1f.x)) * softplus_f(fmaf(a1c.x, G[q].x, c1c.x));
            sy += sigmoid_f(fmaf(a1f.y, F[q].y, c1f.y)) * softplus_f(fmaf(a1c.y, G[q].y, c1c.y));
        }
    }
    for (; e < ee; e++) {
        const __half2* y = (const __half2*)(g_yh + (size_t)e * 128);
        float2 F0 = __half22float2(__ldcs(&y[lane]));
        float2 G0 = __half22float2(__ldcs(&y[32 + lane]));
        sx += sigmoid_f(fmaf(a1f.x, F0.x, c1f.x)) * softplus_f(fmaf(a1c.x, G0.x, c1c.x));
        sy += sigmoid_f(fmaf(a1f.y, F0.y, c1f.y)) * softplus_f(fmaf(a1c.y, G0.y, c1c.y));
    }
    ((float2*)g_ns)[(size_t)a * 32 + lane] = make_float2(sx, sy);
}

// ---------------- BN2 + final ----------------
__global__ __launch_bounds__(256) void k_bn2s(int N) {
    __shared__ float ss[256], sq2[256];
    int f = threadIdx.x & 63;
    int r = threadIdx.x >> 6;
    float s = 0.f, q = 0.f;
    for (int a = blockIdx.x * 4 + r; a < N; a += gridDim.x * 4) {
        float v = g_ns[(size_t)a * 64 + f];
        s += v; q += v * v;
    }
    ss[threadIdx.x] = s; sq2[threadIdx.x] = q;
    __syncthreads();
    if (r == 0) {
        s = ss[f] + ss[64 + f] + ss[128 + f] + ss[192 + f];
        q = sq2[f] + sq2[64 + f] + sq2[128 + f] + sq2[192 + f];
        atomicAdd(&g_bn2s[f], s);
        atomicAdd(&g_bn2q[f], q);
    }
}

__global__ void k_bn2f(const float* __restrict__ gamma2,
                       const float* __restrict__ beta2, int N) {
    int f = threadIdx.x;  // 64
    float inv_n = 1.0f / (float)N;
    float mean = g_bn2s[f] * inv_n;
    float var  = g_bn2q[f] * inv_n - mean * mean;
    float inv  = rsqrtf(var + BN_EPS);
    float a = gamma2[f] * inv;
    g_a2[f] = a;
    g_c2[f] = beta2[f] - a * mean;
}

__global__ void k_final(const float* __restrict__ atom, float* __restrict__ out, int N) {
    int i = blockIdx.x * blockDim.x + threadIdx.x;
    if (i >= N * 64) return;
    int f = i & 63;
    float v = atom[i] + g_a2[f] * g_ns[i] + g_c2[f];
    out[i] = softplus_f(v);
}

// ---------------- launch ----------------
extern "C" void kernel_launch(void* const* d_in, const int* in_sizes, int n_in,
                              void* d_out, int out_size) {
    const float* atom   = (const float*)d_in[0];
    const float* nbr    = (const float*)d_in[1];
    const int*   sidx   = (const int*)d_in[2];
    const int*   nidx   = (const int*)d_in[3];
    const float* W      = (const float*)d_in[4];
    const float* bias   = (const float*)d_in[5];
    const float* gamma1 = (const float*)d_in[6];
    const float* beta1  = (const float*)d_in[7];
    const float* gamma2 = (const float*)d_in[8];
    const float* beta2  = (const float*)d_in[9];
    float* out = (float*)d_out;

    int N = in_sizes[0] / 64;
    int E = in_sizes[2];
    int ET = (E + 127) / 128;

    cudaFuncSetAttribute(k_edge_mma, cudaFuncAttributeMaxDynamicSharedMemorySize, ESMEM);

    k_init<<<(N + 256) / 256, 256>>>(N, E);
    k_proj<<<(N + 63) / 64, 256>>>(atom, W,            0, N);
    k_proj<<<(N + 63) / 64, 256>>>(atom, W + 64 * 128, 1, N);
    k_edge_mma<<<296, 256, ESMEM>>>(nbr, sidx, nidx, W, bias, E, ET);
    k_bn1f<<<1, 128>>>(gamma1, beta1, E);
    k_csr<<<(E + 255) / 256, 256>>>(sidx, E);
    k_atom<<<(N + 7) / 8, 256>>>(N);
    k_bn2s<<<120, 256>>>(N);
    k_bn2f<<<1, 64>>>(gamma2, beta2, N);
    k_final<<<(N * 64 + 255) / 256, 256>>>(atom, out, N);
}

// round 8
// speedup vs baseline: 2.0136x; 1.0752x over previous
#include <cuda_runtime.h>
#include <cuda_fp16.h>
#include <cuda_bf16.h>
#include <math.h>

#define ATOMS_MAX 50000
#define EDGES_MAX 1600000
#define BN_EPS 1e-5f

// ---------------- scratch (device globals) ----------------
__device__ __align__(16) float g_Pself[ATOMS_MAX * 128];            // 25.6 MB
__device__ __align__(16) float g_Pnbr [ATOMS_MAX * 128];            // 25.6 MB
__device__ __align__(16) __half g_yh[(size_t)EDGES_MAX * 128];      // 410 MB
__device__ __align__(16) float g_ns[ATOMS_MAX * 64];                // 12.8 MB
__device__ int   g_start[ATOMS_MAX + 1];
__device__ float g_bn1s[128], g_bn1q[128], g_a1[128], g_c1[128];
__device__ float g_bn2s[64],  g_bn2q[64],  g_a2[64],  g_c2[64];

__device__ __forceinline__ float sigmoid_f(float x) { return 1.0f / (1.0f + __expf(-x)); }
__device__ __forceinline__ float softplus_f(float x) { return fmaxf(x, 0.0f) + log1pf(__expf(-fabsf(x))); }

// ---------------- helpers ----------------
__device__ __forceinline__ unsigned smem_u32(const void* p) {
    unsigned a;
    asm("{ .reg .u64 t; cvta.to.shared.u64 t, %1; cvt.u32.u64 %0, t; }" : "=r"(a) : "l"(p));
    return a;
}
__device__ __forceinline__ void bf16split(float v, unsigned short& h, unsigned short& l) {
    __nv_bfloat16 hb = __float2bfloat16(v);
    __nv_bfloat16 lb = __float2bfloat16(v - __bfloat162float(hb));
    h = __bfloat16_as_ushort(hb);
    l = __bfloat16_as_ushort(lb);
}
__device__ __forceinline__ void ldm_x4(unsigned* r, unsigned addr) {
    asm volatile("ldmatrix.sync.aligned.m8n8.x4.shared.b16 {%0,%1,%2,%3}, [%4];"
                 : "=r"(r[0]), "=r"(r[1]), "=r"(r[2]), "=r"(r[3]) : "r"(addr));
}
__device__ __forceinline__ void ldm_x2(unsigned& r0, unsigned& r1, unsigned addr) {
    asm volatile("ldmatrix.sync.aligned.m8n8.x2.shared.b16 {%0,%1}, [%2];"
                 : "=r"(r0), "=r"(r1) : "r"(addr));
}
__device__ __forceinline__ void mma16816(float* c, const unsigned* a, unsigned b0, unsigned b1) {
    asm volatile(
        "mma.sync.aligned.m16n8k16.row.col.f32.bf16.bf16.f32 "
        "{%0,%1,%2,%3}, {%4,%5,%6,%7}, {%8,%9}, {%0,%1,%2,%3};"
        : "+f"(c[0]), "+f"(c[1]), "+f"(c[2]), "+f"(c[3])
        : "r"(a[0]), "r"(a[1]), "r"(a[2]), "r"(a[3]), "r"(b0), "r"(b1));
}

// ---------------- k_init ----------------
__global__ void k_init(int N, int E) {
    int i = blockIdx.x * blockDim.x + threadIdx.x;
    if (i < 128) { g_bn1s[i] = 0.f; g_bn1q[i] = 0.f; }
    if (i < 64)  { g_bn2s[i] = 0.f; g_bn2q[i] = 0.f; }
    if (i <= N)  g_start[i] = E;
}

// ---------------- k_proj: P = atom(N,64) @ Wp(64,128) ----------------
__global__ __launch_bounds__(256) void k_proj(const float* __restrict__ atom,
                                              const float* __restrict__ Wp,
                                              int which, int N) {
    __shared__ __align__(16) float sW[64 * 128];
    __shared__ float sA[64 * 33];
    float* __restrict__ P = which ? g_Pnbr : g_Pself;

    int tid = threadIdx.x;
    int a0 = blockIdx.x * 64;
    for (int i = tid; i < 64 * 128; i += 256) sW[i] = Wp[i];

    int tx = tid & 15, ty = tid >> 4;
    int n0 = tx * 8, m0 = ty * 4;
    float acc[4][8];
#pragma unroll
    for (int i = 0; i < 4; i++)
#pragma unroll
        for (int j = 0; j < 8; j++) acc[i][j] = 0.f;

    for (int kc = 0; kc < 64; kc += 32) {
        __syncthreads();
        for (int i = tid; i < 64 * 32; i += 256) {
            int m = i >> 5, k = i & 31;
            int a = a0 + m;
            sA[m * 33 + k] = (a < N) ? atom[(size_t)a * 64 + kc + k] : 0.f;
        }
        __syncthreads();
#pragma unroll 8
        for (int k = 0; k < 32; k++) {
            float4 b0 = *(const float4*)&sW[(kc + k) * 128 + n0];
            float4 b1 = *(const float4*)&sW[(kc + k) * 128 + n0 + 4];
            float b[8] = {b0.x, b0.y, b0.z, b0.w, b1.x, b1.y, b1.z, b1.w};
#pragma unroll
            for (int i = 0; i < 4; i++) {
                float av = sA[(m0 + i) * 33 + k];
#pragma unroll
                for (int j = 0; j < 8; j++) acc[i][j] = fmaf(av, b[j], acc[i][j]);
            }
        }
    }
#pragma unroll
    for (int i = 0; i < 4; i++) {
        int a = a0 + m0 + i;
        if (a < N) {
            *(float4*)&P[(size_t)a * 128 + n0] =
                make_float4(acc[i][0], acc[i][1], acc[i][2], acc[i][3]);
            *(float4*)&P[(size_t)a * 128 + n0 + 4] =
                make_float4(acc[i][4], acc[i][5], acc[i][6], acc[i][7]);
        }
    }
}

// ---------------- k_edge_mma v5: 64x128 tiles, 3 CTAs/SM ----------------
// smem: [0..256) sidx, [256..512) nidx,
// [512..9728)   sA (64 x 72 bf16, 144B stride)
// [9728..28160) sB (128 x 72 bf16, 144B)
// [28160..45056) sY (32 x 132 fp32, 528B)
#define EOFF_S   0
#define EOFF_N   256
#define EOFF_A   512
#define EOFF_B   9728
#define EOFF_Y   28160
#define ESMEM    (28160 + 32 * 132 * 4)    // 45056
#define ASTRIDE  72     // ushorts per row (144 bytes)
#define YSTRIDE  132    // floats per row (528 bytes)

__global__ __launch_bounds__(256, 3) void k_edge_mma(const float* __restrict__ nbr,
                                                     const int* __restrict__ sidx,
                                                     const int* __restrict__ nidx,
                                                     const float* __restrict__ W,
                                                     const float* __restrict__ bias,
                                                     int E, int ET) {
    extern __shared__ char sm[];
    int*   sS = (int*)(sm + EOFF_S);
    int*   sN = (int*)(sm + EOFF_N);
    unsigned short* sA = (unsigned short*)(sm + EOFF_A);
    unsigned short* sB = (unsigned short*)(sm + EOFF_B);
    float* sY = (float*)(sm + EOFF_Y);

    int tid = threadIdx.x;
    int wid = tid >> 5;
    int lane = tid & 31;

    // build B = [Whi(k0..31) | Wlo(k0..31)] per output row n (bf16 hi/lo split)
    for (int i = tid; i < 128 * 32; i += 256) {
        int n = i >> 5, k = i & 31;
        float w = W[(128 + k) * 128 + n];
        unsigned short hi, lo;
        bf16split(w, hi, lo);
        sB[n * ASTRIDE + k]      = hi;
        sB[n * ASTRIDE + 32 + k] = lo;
    }
    float4 biasv = ((const float4*)bias)[lane];   // cols lane*4..lane*4+3

    int g = wid >> 1;      // m-group: rows g*16..g*16+15
    int h = wid & 1;       // n-half: cols h*64..h*64+63

    unsigned aBase = smem_u32(sA);
    unsigned bBase = smem_u32(sB);

    int arow = g * 16 + (lane & 7) + ((lane >> 3) & 1) * 8;
    int acol8 = (lane >> 4);
    unsigned bRowOff = (unsigned)((h * 64 + (lane & 7)) * 144 + ((lane >> 3) & 1) * 16);

    // BN1 stat accumulators (cols lane*4..lane*4+3)
    float4 st = make_float4(0.f, 0.f, 0.f, 0.f);
    float4 sq = make_float4(0.f, 0.f, 0.f, 0.f);

    for (int tile = blockIdx.x; tile < ET; tile += gridDim.x) {
        int e0 = tile * 64;
        __syncthreads();   // smem reuse vs previous epilogue / B build

        // ---- A tile: 64 edges x 32 fp32 -> [hi(0-31)|lo(32-63)] bf16 ----
        {
            int row = tid >> 2, part = tid & 3;   // 2 float4 per thread
            int e = e0 + row;
            bool v = e < E;
            const float4* src = (const float4*)(nbr + (size_t)e * 32 + part * 8);
            unsigned short* dst = sA + row * ASTRIDE + part * 8;
#pragma unroll
            for (int j = 0; j < 2; j++) {
                float4 x = v ? src[j] : make_float4(0.f, 0.f, 0.f, 0.f);
                unsigned short h0, l0, h1, l1, h2, l2, h3, l3;
                bf16split(x.x, h0, l0); bf16split(x.y, h1, l1);
                bf16split(x.z, h2, l2); bf16split(x.w, h3, l3);
                uint2 hp, lp;
                hp.x = (unsigned)h0 | ((unsigned)h1 << 16);
                hp.y = (unsigned)h2 | ((unsigned)h3 << 16);
                lp.x = (unsigned)l0 | ((unsigned)l1 << 16);
                lp.y = (unsigned)l2 | ((unsigned)l3 << 16);
                *(uint2*)(dst + j * 4)      = hp;
                *(uint2*)(dst + 32 + j * 4) = lp;
            }
            if (tid < 64) {
                int e2 = e0 + tid;
                sS[tid] = (e2 < E) ? sidx[e2] : 0;
                sN[tid] = (e2 < E) ? nidx[e2] : 0;
            }
        }
        __syncthreads();

        // ---- MMA: pass1 Σ A_j·B_j + pass2 Σ A_{j^2}·B_j (exact bf16 split) ----
        float acc[8][4];
#pragma unroll
        for (int nt = 0; nt < 8; nt++)
#pragma unroll
            for (int r = 0; r < 4; r++) acc[nt][r] = 0.f;

#pragma unroll
        for (int j = 0; j < 4; j++) {
            unsigned a1f[4], a2f[4];
            unsigned base = aBase + (unsigned)(arow * 144);
            ldm_x4(a1f, base + (unsigned)((j * 16 + 8 * acol8) * 2));
            ldm_x4(a2f, base + (unsigned)(((j ^ 2) * 16 + 8 * acol8) * 2));
#pragma unroll
            for (int nt = 0; nt < 8; nt++) {
                unsigned b0, b1;
                ldm_x2(b0, b1, bBase + bRowOff + (unsigned)(j * 32 + nt * 8 * 144));
                mma16816(acc[nt], a1f, b0, b1);
                mma16816(acc[nt], a2f, b0, b1);
            }
        }

        // ---- two epilogue waves of 32 rows through the 32-row sY buffer ----
#pragma unroll
        for (int wave = 0; wave < 2; wave++) {
            // stage: m-groups {wave*2, wave*2+1}
            if ((g >> 1) == wave) {
                int rq = lane >> 2, cq = lane & 3;
                int gl = g & 1;                     // 0/1 within wave
                int r0 = gl * 16 + rq;              // sY row
#pragma unroll
                for (int nt = 0; nt < 8; nt++) {
                    int c = h * 64 + nt * 8 + 2 * cq;
                    *(float2*)&sY[r0 * YSTRIDE + c]       = make_float2(acc[nt][0], acc[nt][1]);
                    *(float2*)&sY[(r0 + 8) * YSTRIDE + c] = make_float2(acc[nt][2], acc[nt][3]);
                }
            }
            __syncthreads();
            // epilogue: 32 rows, warp w -> rows w*4..w*4+3
#pragma unroll
            for (int i = 0; i < 4; i++) {
                int yrow = wid * 4 + i;            // 0..31
                int row = wave * 32 + yrow;        // tile row
                int e = e0 + row;
                if (e >= E) continue;
                int s = sS[row], n = sN[row];
                float4 a4 = *(const float4*)&sY[yrow * YSTRIDE + lane * 4];
                float4 ps = ((const float4*)(g_Pself + (size_t)s * 128))[lane];
                float4 pn = ((const float4*)(g_Pnbr + (size_t)n * 128))[lane];
                float y0 = a4.x + ps.x + pn.x + biasv.x;
                float y1 = a4.y + ps.y + pn.y + biasv.y;
                float y2 = a4.z + ps.z + pn.z + biasv.z;
                float y3 = a4.w + ps.w + pn.w + biasv.w;
                st.x += y0; st.y += y1; st.z += y2; st.w += y3;
                sq.x += y0 * y0; sq.y += y1 * y1; sq.z += y2 * y2; sq.w += y3 * y3;
                __half2 p01 = __floats2half2_rn(y0, y1);
                __half2 p23 = __floats2half2_rn(y2, y3);
                uint2 u;
                u.x = *(unsigned*)&p01;
                u.y = *(unsigned*)&p23;
                __stcs((uint2*)(g_yh + (size_t)e * 128 + lane * 4), u);
            }
            __syncthreads();
        }
    }

    // ---- BN1 stats: cross-warp reduce in smem, one atomicAdd per col per CTA ----
    __syncthreads();
    *(float4*)&sY[wid * 128 + lane * 4] = st;
    *(float4*)&sY[1024 + wid * 128 + lane * 4] = sq;
    __syncthreads();
    if (tid < 128) {
        float a = 0.f, b = 0.f;
#pragma unroll
        for (int w = 0; w < 8; w++) {
            a += sY[w * 128 + tid];
            b += sY[1024 + w * 128 + tid];
        }
        atomicAdd(&g_bn1s[tid], a);
        atomicAdd(&g_bn1q[tid], b);
    }
}

// ---------------- k_bn1f ----------------
__global__ void k_bn1f(const float* __restrict__ gamma1,
                       const float* __restrict__ beta1, int E) {
    int f = threadIdx.x;  // 128
    float inv_n = 1.0f / (float)E;
    float mean = g_bn1s[f] * inv_n;
    float var  = g_bn1q[f] * inv_n - mean * mean;
    float inv  = rsqrtf(var + BN_EPS);
    float a = gamma1[f] * inv;
    g_a1[f] = a;
    g_c1[f] = beta1[f] - a * mean;
}

// ---------------- k_csr ----------------
__global__ void k_csr(const int* __restrict__ sidx, int E) {
    int e = blockIdx.x * blockDim.x + threadIdx.x;
    if (e >= E) return;
    int cur = sidx[e];
    int prev = (e == 0) ? -1 : sidx[e - 1];
    for (int a = prev + 1; a <= cur; a++) g_start[a] = e;
}

// ---------------- k_atom: message + segment sum (warp/atom, 4x unroll) ----------
__global__ __launch_bounds__(256) void k_atom(int N) {
    int warp = (blockIdx.x * blockDim.x + threadIdx.x) >> 5;
    int lane = threadIdx.x & 31;
    if (warp >= N) return;
    int a = warp;

    float2 a1f = ((const float2*)g_a1)[lane];
    float2 c1f = ((const float2*)g_c1)[lane];
    float2 a1c = ((const float2*)g_a1)[32 + lane];
    float2 c1c = ((const float2*)g_c1)[32 + lane];

    float sx = 0.f, sy = 0.f;
    int eb = g_start[a], ee = g_start[a + 1];
    int e = eb;
    for (; e + 4 <= ee; e += 4) {
        float2 F[4], G[4];
#pragma unroll
        for (int q = 0; q < 4; q++) {
            const __half2* y = (const __half2*)(g_yh + (size_t)(e + q) * 128);
            __half2 hf = __ldcs(&y[lane]);
            __half2 hg = __ldcs(&y[32 + lane]);
            F[q] = __half22float2(hf);
            G[q] = __half22float2(hg);
        }
#pragma unroll
        for (int q = 0; q < 4; q++) {
            sx += sigmoid_f(fmaf(a1f.x, F[q].x, c1f.x)) * softplus_f(fmaf(a1c.x, G[q].x, c1c.x));
            sy += sigmoid_f(fmaf(a1f.y, F[q].y, c1f.y)) * softplus_f(fmaf(a1c.y, G[q].y, c1c.y));
        }
    }
    for (; e < ee; e++) {
        const __half2* y = (const __half2*)(g_yh + (size_t)e * 128);
        float2 F0 = __half22float2(__ldcs(&y[lane]));
        float2 G0 = __half22float2(__ldcs(&y[32 + lane]));
        sx += sigmoid_f(fmaf(a1f.x, F0.x, c1f.x)) * softplus_f(fmaf(a1c.x, G0.x, c1c.x));
        sy += sigmoid_f(fmaf(a1f.y, F0.y, c1f.y)) * softplus_f(fmaf(a1c.y, G0.y, c1c.y));
    }
    ((float2*)g_ns)[(size_t)a * 32 + lane] = make_float2(sx, sy);
}

// ---------------- BN2 + final ----------------
__global__ __launch_bounds__(256) void k_bn2s(int N) {
    __shared__ float ss[256], sq2[256];
    int f = threadIdx.x & 63;
    int r = threadIdx.x >> 6;
    float s = 0.f, q = 0.f;
    for (int a = blockIdx.x * 4 + r; a < N; a += gridDim.x * 4) {
        float v = g_ns[(size_t)a * 64 + f];
        s += v; q += v * v;
    }
    ss[threadIdx.x] = s; sq2[threadIdx.x] = q;
    __syncthreads();
    if (r == 0) {
        s = ss[f] + ss[64 + f] + ss[128 + f] + ss[192 + f];
        q = sq2[f] + sq2[64 + f] + sq2[128 + f] + sq2[192 + f];
        atomicAdd(&g_bn2s[f], s);
        atomicAdd(&g_bn2q[f], q);
    }
}

__global__ void k_bn2f(const float* __restrict__ gamma2,
                       const float* __restrict__ beta2, int N) {
    int f = threadIdx.x;  // 64
    float inv_n = 1.0f / (float)N;
    float mean = g_bn2s[f] * inv_n;
    float var  = g_bn2q[f] * inv_n - mean * mean;
    float inv  = rsqrtf(var + BN_EPS);
    float a = gamma2[f] * inv;
    g_a2[f] = a;
    g_c2[f] = beta2[f] - a * mean;
}

__global__ void k_final(const float* __restrict__ atom, float* __restrict__ out, int N) {
    int i = blockIdx.x * blockDim.x + threadIdx.x;
    if (i >= N * 64) return;
    int f = i & 63;
    float v = atom[i] + g_a2[f] * g_ns[i] + g_c2[f];
    out[i] = softplus_f(v);
}

// ---------------- launch ----------------
extern "C" void kernel_launch(void* const* d_in, const int* in_sizes, int n_in,
                              void* d_out, int out_size) {
    const float* atom   = (const float*)d_in[0];
    const float* nbr    = (const float*)d_in[1];
    const int*   sidx   = (const int*)d_in[2];
    const int*   nidx   = (const int*)d_in[3];
    const float* W      = (const float*)d_in[4];
    const float* bias   = (const float*)d_in[5];
    const float* gamma1 = (const float*)d_in[6];
    const float* beta1  = (const float*)d_in[7];
    const float* gamma2 = (const float*)d_in[8];
    const float* beta2  = (const float*)d_in[9];
    float* out = (float*)d_out;

    int N = in_sizes[0] / 64;
    int E = in_sizes[2];
    int ET = (E + 63) / 64;

    cudaFuncSetAttribute(k_edge_mma, cudaFuncAttributeMaxDynamicSharedMemorySize, ESMEM);

    k_init<<<(N + 256) / 256, 256>>>(N, E);
    k_proj<<<(N + 63) / 64, 256>>>(atom, W,            0, N);
    k_proj<<<(N + 63) / 64, 256>>>(atom, W + 64 * 128, 1, N);
    k_edge_mma<<<444, 256, ESMEM>>>(nbr, sidx, nidx, W, bias, E, ET);
    k_bn1f<<<1, 128>>>(gamma1, beta1, E);
    k_csr<<<(E + 255) / 256, 256>>>(sidx, E);
    k_atom<<<(N + 7) / 8, 256>>>(N);
    k_bn2s<<<120, 256>>>(N);
    k_bn2f<<<1, 64>>>(gamma2, beta2, N);
    k_final<<<(N * 64 + 255) / 256, 256>>>(atom, out, N);
}

// round 9
// speedup vs baseline: 2.3990x; 1.1914x over previous
#include <cuda_runtime.h>
#include <cuda_fp16.h>
#include <cuda_bf16.h>
#include <math.h>

#define ATOMS_MAX 50000
#define EDGES_MAX 1600000
#define BN_EPS 1e-5f

// ---------------- scratch (device globals) ----------------
__device__ __align__(16) float g_Pself[ATOMS_MAX * 128];            // 25.6 MB (bias folded in)
__device__ __align__(16) float g_Pnbr [ATOMS_MAX * 128];            // 25.6 MB
__device__ __align__(16) __half g_yh[(size_t)EDGES_MAX * 128];      // 410 MB
__device__ __align__(16) float g_ns[ATOMS_MAX * 64];                // 12.8 MB
__device__ int   g_start[ATOMS_MAX + 1];
__device__ float g_bn1s[128], g_bn1q[128], g_a1[128], g_c1[128];
__device__ float g_bn2s[64],  g_bn2q[64],  g_a2[64],  g_c2[64];

__device__ __forceinline__ float sigmoid_f(float x) {
    return __fdividef(1.0f, 1.0f + __expf(-x));
}
__device__ __forceinline__ float softplus_f(float x) {
    return fmaxf(x, 0.0f) + __logf(1.0f + __expf(-fabsf(x)));
}

// ---------------- helpers ----------------
__device__ __forceinline__ unsigned smem_u32(const void* p) {
    unsigned a;
    asm("{ .reg .u64 t; cvta.to.shared.u64 t, %1; cvt.u32.u64 %0, t; }" : "=r"(a) : "l"(p));
    return a;
}
__device__ __forceinline__ void bf16split(float v, unsigned short& h, unsigned short& l) {
    __nv_bfloat16 hb = __float2bfloat16(v);
    __nv_bfloat16 lb = __float2bfloat16(v - __bfloat162float(hb));
    h = __bfloat16_as_ushort(hb);
    l = __bfloat16_as_ushort(lb);
}
__device__ __forceinline__ void ldm_x4(unsigned* r, unsigned addr) {
    asm volatile("ldmatrix.sync.aligned.m8n8.x4.shared.b16 {%0,%1,%2,%3}, [%4];"
                 : "=r"(r[0]), "=r"(r[1]), "=r"(r[2]), "=r"(r[3]) : "r"(addr));
}
__device__ __forceinline__ void mma16816(float* c, const unsigned* a, unsigned b0, unsigned b1) {
    asm volatile(
        "mma.sync.aligned.m16n8k16.row.col.f32.bf16.bf16.f32 "
        "{%0,%1,%2,%3}, {%4,%5,%6,%7}, {%8,%9}, {%0,%1,%2,%3};"
        : "+f"(c[0]), "+f"(c[1]), "+f"(c[2]), "+f"(c[3])
        : "r"(a[0]), "r"(a[1]), "r"(a[2]), "r"(a[3]), "r"(b0), "r"(b1));
}

// ---------------- k_init ----------------
__global__ void k_init(int N, int E) {
    int i = blockIdx.x * blockDim.x + threadIdx.x;
    if (i < 128) { g_bn1s[i] = 0.f; g_bn1q[i] = 0.f; }
    if (i < 64)  { g_bn2s[i] = 0.f; g_bn2q[i] = 0.f; }
    if (i <= N)  g_start[i] = E;
}

// ---------------- k_proj: P = atom(N,64) @ Wp(64,128)  (+bias when which==0) ----
__global__ __launch_bounds__(256) void k_proj(const float* __restrict__ atom,
                                              const float* __restrict__ Wp,
                                              const float* __restrict__ bias,
                                              int which, int N) {
    __shared__ __align__(16) float sW[64 * 128];
    __shared__ float sA[64 * 33];
    float* __restrict__ P = which ? g_Pnbr : g_Pself;

    int tid = threadIdx.x;
    int a0 = blockIdx.x * 64;
    for (int i = tid; i < 64 * 128; i += 256) sW[i] = Wp[i];

    int tx = tid & 15, ty = tid >> 4;
    int n0 = tx * 8, m0 = ty * 4;
    float acc[4][8];
#pragma unroll
    for (int i = 0; i < 4; i++)
#pragma unroll
        for (int j = 0; j < 8; j++) acc[i][j] = 0.f;

    for (int kc = 0; kc < 64; kc += 32) {
        __syncthreads();
        for (int i = tid; i < 64 * 32; i += 256) {
            int m = i >> 5, k = i & 31;
            int a = a0 + m;
            sA[m * 33 + k] = (a < N) ? atom[(size_t)a * 64 + kc + k] : 0.f;
        }
        __syncthreads();
#pragma unroll 8
        for (int k = 0; k < 32; k++) {
            float4 b0 = *(const float4*)&sW[(kc + k) * 128 + n0];
            float4 b1 = *(const float4*)&sW[(kc + k) * 128 + n0 + 4];
            float b[8] = {b0.x, b0.y, b0.z, b0.w, b1.x, b1.y, b1.z, b1.w};
#pragma unroll
            for (int i = 0; i < 4; i++) {
                float av = sA[(m0 + i) * 33 + k];
#pragma unroll
                for (int j = 0; j < 8; j++) acc[i][j] = fmaf(av, b[j], acc[i][j]);
            }
        }
    }
    float bb[8] = {0.f, 0.f, 0.f, 0.f, 0.f, 0.f, 0.f, 0.f};
    if (which == 0) {
        float4 b0 = *(const float4*)&bias[n0];
        float4 b1 = *(const float4*)&bias[n0 + 4];
        bb[0] = b0.x; bb[1] = b0.y; bb[2] = b0.z; bb[3] = b0.w;
        bb[4] = b1.x; bb[5] = b1.y; bb[6] = b1.z; bb[7] = b1.w;
    }
#pragma unroll
    for (int i = 0; i < 4; i++) {
        int a = a0 + m0 + i;
        if (a < N) {
            *(float4*)&P[(size_t)a * 128 + n0] =
                make_float4(acc[i][0] + bb[0], acc[i][1] + bb[1], acc[i][2] + bb[2], acc[i][3] + bb[3]);
            *(float4*)&P[(size_t)a * 128 + n0 + 4] =
                make_float4(acc[i][4] + bb[4], acc[i][5] + bb[5], acc[i][6] + bb[6], acc[i][7] + bb[7]);
        }
    }
}

// ---------------- k_edge_mma v6: 64x128 tiles, 3 CTAs/SM, ldm_x4 B ----------------
// smem: [0..256) sidx, [256..512) nidx,
// [512..9728)   sA (64 x 72 bf16, 144B stride)
// [9728..28160) sB (128 x 72 bf16, 144B)
// [28160..45056) sY (32 x 132 fp32, 528B)
#define EOFF_S   0
#define EOFF_N   256
#define EOFF_A   512
#define EOFF_B   9728
#define EOFF_Y   28160
#define ESMEM    (28160 + 32 * 132 * 4)    // 45056
#define ASTRIDE  72     // ushorts per row (144 bytes)
#define YSTRIDE  132    // floats per row (528 bytes)

__global__ __launch_bounds__(256, 3) void k_edge_mma(const float* __restrict__ nbr,
                                                     const int* __restrict__ sidx,
                                                     const int* __restrict__ nidx,
                                                     const float* __restrict__ W,
                                                     int E, int ET) {
    extern __shared__ char sm[];
    int*   sS = (int*)(sm + EOFF_S);
    int*   sN = (int*)(sm + EOFF_N);
    unsigned short* sA = (unsigned short*)(sm + EOFF_A);
    unsigned short* sB = (unsigned short*)(sm + EOFF_B);
    float* sY = (float*)(sm + EOFF_Y);

    int tid = threadIdx.x;
    int wid = tid >> 5;
    int lane = tid & 31;

    // build B = [Whi(k0..31) | Wlo(k0..31)] per output row n (bf16 hi/lo split)
    for (int i = tid; i < 128 * 32; i += 256) {
        int n = i >> 5, k = i & 31;
        float w = W[(128 + k) * 128 + n];
        unsigned short hi, lo;
        bf16split(w, hi, lo);
        sB[n * ASTRIDE + k]      = hi;
        sB[n * ASTRIDE + 32 + k] = lo;
    }

    int g = wid >> 1;      // m-group: rows g*16..g*16+15
    int h = wid & 1;       // n-half: cols h*64..h*64+63

    unsigned aBase = smem_u32(sA);
    unsigned bBase = smem_u32(sB);

    int arow = g * 16 + (lane & 7) + ((lane >> 3) & 1) * 8;
    int acol8 = (lane >> 4);
    // x4 B addressing: lanes 0-7 mat0 (n rows, k-half0), 8-15 mat1 (+16B),
    // 16-23 mat2 (n+8 rows), 24-31 mat3 (n+8, +16B)
    unsigned bRowOff4 = (unsigned)((h * 64 + ((lane >> 4) & 1) * 8 + (lane & 7)) * 144
                                   + ((lane >> 3) & 1) * 16);

    // BN1 stat accumulators (cols lane*4..lane*4+3)
    float4 st = make_float4(0.f, 0.f, 0.f, 0.f);
    float4 sq = make_float4(0.f, 0.f, 0.f, 0.f);

    for (int tile = blockIdx.x; tile < ET; tile += gridDim.x) {
        int e0 = tile * 64;
        __syncthreads();   // smem reuse vs previous epilogue / B build

        // ---- A tile: 64 edges x 32 fp32 -> [hi(0-31)|lo(32-63)] bf16 ----
        {
            int row = tid >> 2, part = tid & 3;
            int e = e0 + row;
            bool v = e < E;
            const float4* src = (const float4*)(nbr + (size_t)e * 32 + part * 8);
            unsigned short* dst = sA + row * ASTRIDE + part * 8;
#pragma unroll
            for (int j = 0; j < 2; j++) {
                float4 x = v ? src[j] : make_float4(0.f, 0.f, 0.f, 0.f);
                unsigned short h0, l0, h1, l1, h2, l2, h3, l3;
                bf16split(x.x, h0, l0); bf16split(x.y, h1, l1);
                bf16split(x.z, h2, l2); bf16split(x.w, h3, l3);
                uint2 hp, lp;
                hp.x = (unsigned)h0 | ((unsigned)h1 << 16);
                hp.y = (unsigned)h2 | ((unsigned)h3 << 16);
                lp.x = (unsigned)l0 | ((unsigned)l1 << 16);
                lp.y = (unsigned)l2 | ((unsigned)l3 << 16);
                *(uint2*)(dst + j * 4)      = hp;
                *(uint2*)(dst + 32 + j * 4) = lp;
            }
            if (tid < 64) {
                int e2 = e0 + tid;
                sS[tid] = (e2 < E) ? sidx[e2] : 0;
                sN[tid] = (e2 < E) ? nidx[e2] : 0;
            }
        }
        __syncthreads();

        // ---- MMA: pass1 Σ A_j·B_j + pass2 Σ A_{j^2}·B_j (exact bf16 split) ----
        float acc[8][4];
#pragma unroll
        for (int nt = 0; nt < 8; nt++)
#pragma unroll
            for (int r = 0; r < 4; r++) acc[nt][r] = 0.f;

#pragma unroll
        for (int j = 0; j < 4; j++) {
            unsigned a1f[4], a2f[4];
            unsigned base = aBase + (unsigned)(arow * 144);
            ldm_x4(a1f, base + (unsigned)((j * 16 + 8 * acol8) * 2));
            ldm_x4(a2f, base + (unsigned)(((j ^ 2) * 16 + 8 * acol8) * 2));
#pragma unroll
            for (int p = 0; p < 4; p++) {          // nt pairs: (2p, 2p+1)
                unsigned bf[4];
                ldm_x4(bf, bBase + bRowOff4 + (unsigned)(j * 32 + p * 16 * 144));
                mma16816(acc[2 * p],     a1f, bf[0], bf[1]);
                mma16816(acc[2 * p + 1], a1f, bf[2], bf[3]);
                mma16816(acc[2 * p],     a2f, bf[0], bf[1]);
                mma16816(acc[2 * p + 1], a2f, bf[2], bf[3]);
            }
        }

        // ---- two epilogue waves of 32 rows through the 32-row sY buffer ----
#pragma unroll
        for (int wave = 0; wave < 2; wave++) {
            if ((g >> 1) == wave) {
                int rq = lane >> 2, cq = lane & 3;
                int gl = g & 1;
                int r0 = gl * 16 + rq;
#pragma unroll
                for (int nt = 0; nt < 8; nt++) {
                    int c = h * 64 + nt * 8 + 2 * cq;
                    *(float2*)&sY[r0 * YSTRIDE + c]       = make_float2(acc[nt][0], acc[nt][1]);
                    *(float2*)&sY[(r0 + 8) * YSTRIDE + c] = make_float2(acc[nt][2], acc[nt][3]);
                }
            }
            __syncthreads();
#pragma unroll
            for (int i = 0; i < 4; i++) {
                int yrow = wid * 4 + i;
                int row = wave * 32 + yrow;
                int e = e0 + row;
                if (e >= E) continue;
                int s = sS[row], n = sN[row];
                float4 a4 = *(const float4*)&sY[yrow * YSTRIDE + lane * 4];
                float4 ps = ((const float4*)(g_Pself + (size_t)s * 128))[lane];
                float4 pn = ((const float4*)(g_Pnbr + (size_t)n * 128))[lane];
                float y0 = a4.x + ps.x + pn.x;
                float y1 = a4.y + ps.y + pn.y;
                float y2 = a4.z + ps.z + pn.z;
                float y3 = a4.w + ps.w + pn.w;
                st.x += y0; st.y += y1; st.z += y2; st.w += y3;
                sq.x += y0 * y0; sq.y += y1 * y1; sq.z += y2 * y2; sq.w += y3 * y3;
                __half2 p01 = __floats2half2_rn(y0, y1);
                __half2 p23 = __floats2half2_rn(y2, y3);
                uint2 u;
                u.x = *(unsigned*)&p01;
                u.y = *(unsigned*)&p23;
                __stcs((uint2*)(g_yh + (size_t)e * 128 + lane * 4), u);
            }
            __syncthreads();
        }
    }

    // ---- BN1 stats: cross-warp reduce in smem, one atomicAdd per col per CTA ----
    __syncthreads();
    *(float4*)&sY[wid * 128 + lane * 4] = st;
    *(float4*)&sY[1024 + wid * 128 + lane * 4] = sq;
    __syncthreads();
    if (tid < 128) {
        float a = 0.f, b = 0.f;
#pragma unroll
        for (int w = 0; w < 8; w++) {
            a += sY[w * 128 + tid];
            b += sY[1024 + w * 128 + tid];
        }
        atomicAdd(&g_bn1s[tid], a);
        atomicAdd(&g_bn1q[tid], b);
    }
}

// ---------------- k_bn1f ----------------
__global__ void k_bn1f(const float* __restrict__ gamma1,
                       const float* __restrict__ beta1, int E) {
    int f = threadIdx.x;  // 128
    float inv_n = 1.0f / (float)E;
    float mean = g_bn1s[f] * inv_n;
    float var  = g_bn1q[f] * inv_n - mean * mean;
    float inv  = rsqrtf(var + BN_EPS);
    float a = gamma1[f] * inv;
    g_a1[f] = a;
    g_c1[f] = beta1[f] - a * mean;
}

// ---------------- k_csr ----------------
__global__ void k_csr(const int* __restrict__ sidx, int E) {
    int e = blockIdx.x * blockDim.x + threadIdx.x;
    if (e >= E) return;
    int cur = sidx[e];
    int prev = (e == 0) ? -1 : sidx[e - 1];
    for (int a = prev + 1; a <= cur; a++) g_start[a] = e;
}

// ---------------- k_atom: message + segment sum (warp/atom, fast transcendentals) --
__global__ __launch_bounds__(256) void k_atom(int N) {
    int warp = (blockIdx.x * blockDim.x + threadIdx.x) >> 5;
    int lane = threadIdx.x & 31;
    if (warp >= N) return;
    int a = warp;

    float2 a1f = ((const float2*)g_a1)[lane];
    float2 c1f = ((const float2*)g_c1)[lane];
    float2 a1c = ((const float2*)g_a1)[32 + lane];
    float2 c1c = ((const float2*)g_c1)[32 + lane];

    float sx = 0.f, sy = 0.f;
    int eb = g_start[a], ee = g_start[a + 1];
    int e = eb;
    for (; e + 4 <= ee; e += 4) {
        float2 F[4], G[4];
#pragma unroll
        for (int q = 0; q < 4; q++) {
            const __half2* y = (const __half2*)(g_yh + (size_t)(e + q) * 128);
            F[q] = __half22float2(__ldcs(&y[lane]));
            G[q] = __half22float2(__ldcs(&y[32 + lane]));
        }
#pragma unroll
        for (int q = 0; q < 4; q++) {
            sx += sigmoid_f(fmaf(a1f.x, F[q].x, c1f.x)) * softplus_f(fmaf(a1c.x, G[q].x, c1c.x));
            sy += sigmoid_f(fmaf(a1f.y, F[q].y, c1f.y)) * softplus_f(fmaf(a1c.y, G[q].y, c1c.y));
        }
    }
    for (; e < ee; e++) {
        const __half2* y = (const __half2*)(g_yh + (size_t)e * 128);
        float2 F0 = __half22float2(__ldcs(&y[lane]));
        float2 G0 = __half22float2(__ldcs(&y[32 + lane]));
        sx += sigmoid_f(fmaf(a1f.x, F0.x, c1f.x)) * softplus_f(fmaf(a1c.x, G0.x, c1c.x));
        sy += sigmoid_f(fmaf(a1f.y, F0.y, c1f.y)) * softplus_f(fmaf(a1c.y, G0.y, c1c.y));
    }
    ((float2*)g_ns)[(size_t)a * 32 + lane] = make_float2(sx, sy);
}

// ---------------- BN2 + final ----------------
__global__ __launch_bounds__(256) void k_bn2s(int N) {
    __shared__ float ss[256], sq2[256];
    int f = threadIdx.x & 63;
    int r = threadIdx.x >> 6;
    float s = 0.f, q = 0.f;
    for (int a = blockIdx.x * 4 + r; a < N; a += gridDim.x * 4) {
        float v = g_ns[(size_t)a * 64 + f];
        s += v; q += v * v;
    }
    ss[threadIdx.x] = s; sq2[threadIdx.x] = q;
    __syncthreads();
    if (r == 0) {
        s = ss[f] + ss[64 + f] + ss[128 + f] + ss[192 + f];
        q = sq2[f] + sq2[64 + f] + sq2[128 + f] + sq2[192 + f];
        atomicAdd(&g_bn2s[f], s);
        atomicAdd(&g_bn2q[f], q);
    }
}

__global__ void k_bn2f(const float* __restrict__ gamma2,
                       const float* __restrict__ beta2, int N) {
    int f = threadIdx.x;  // 64
    float inv_n = 1.0f / (float)N;
    float mean = g_bn2s[f] * inv_n;
    float var  = g_bn2q[f] * inv_n - mean * mean;
    float inv  = rsqrtf(var + BN_EPS);
    float a = gamma2[f] * inv;
    g_a2[f] = a;
    g_c2[f] = beta2[f] - a * mean;
}

__global__ void k_final(const float* __restrict__ atom, float* __restrict__ out, int N) {
    int i = blockIdx.x * blockDim.x + threadIdx.x;
    if (i >= N * 64) return;
    int f = i & 63;
    float v = atom[i] + g_a2[f] * g_ns[i] + g_c2[f];
    out[i] = softplus_f(v);
}

// ---------------- launch ----------------
extern "C" void kernel_launch(void* const* d_in, const int* in_sizes, int n_in,
                              void* d_out, int out_size) {
    const float* atom   = (const float*)d_in[0];
    const float* nbr    = (const float*)d_in[1];
    const int*   sidx   = (const int*)d_in[2];
    const int*   nidx   = (const int*)d_in[3];
    const float* W      = (const float*)d_in[4];
    const float* bias   = (const float*)d_in[5];
    const float* gamma1 = (const float*)d_in[6];
    const float* beta1  = (const float*)d_in[7];
    const float* gamma2 = (const float*)d_in[8];
    const float* beta2  = (const float*)d_in[9];
    float* out = (float*)d_out;

    int N = in_sizes[0] / 64;
    int E = in_sizes[2];
    int ET = (E + 63) / 64;

    cudaFuncSetAttribute(k_edge_mma, cudaFuncAttributeMaxDynamicSharedMemorySize, ESMEM);

    k_init<<<(N + 256) / 256, 256>>>(N, E);
    k_proj<<<(N + 63) / 64, 256>>>(atom, W,            bias, 0, N);
    k_proj<<<(N + 63) / 64, 256>>>(atom, W + 64 * 128, bias, 1, N);
    k_edge_mma<<<444, 256, ESMEM>>>(nbr, sidx, nidx, W, E, ET);
    k_bn1f<<<1, 128>>>(gamma1, beta1, E);
    k_csr<<<(E + 255) / 256, 256>>>(sidx, E);
    k_atom<<<(N + 7) / 8, 256>>>(N);
    k_bn2s<<<120, 256>>>(N);
    k_bn2f<<<1, 64>>>(gamma2, beta2, N);
    k_final<<<(N * 64 + 255) / 256, 256>>>(atom, out, N);
}